// round 10
// baseline (speedup 1.0000x reference)
#include <cuda_runtime.h>
#include <math.h>

#define NCB   64
#define CDIM  256
#define DDIM  64
#define KDIM  32
#define ALPHA 8
#define HDIM  256
#define MODI  225   // K + 3D + 1
#define MODO  97    // K + 1 + D

__device__ __forceinline__ float sigm(float x) { return 1.0f / (1.0f + expf(-x)); }

// packed f32x2 helpers (Blackwell fma.rn.f32x2 / add.rn.f32x2 — not emitted by ptxas from C++)
__device__ __forceinline__ unsigned long long pk(float x, float y) {
    unsigned long long u;
    asm("mov.b64 %0, {%1, %2};" : "=l"(u) : "f"(x), "f"(y));
    return u;
}
__device__ __forceinline__ unsigned long long ffma2u(unsigned long long a, unsigned long long b, unsigned long long c) {
    unsigned long long d;
    asm("fma.rn.f32x2 %0, %1, %2, %3;" : "=l"(d) : "l"(a), "l"(b), "l"(c));
    return d;
}
__device__ __forceinline__ unsigned long long add2u(unsigned long long a, unsigned long long b) {
    unsigned long long d;
    asm("add.rn.f32x2 %0, %1, %2;" : "=l"(d) : "l"(a), "l"(b));
    return d;
}

// TMA bulk-copy helpers
__device__ __forceinline__ unsigned smem_u32(const void* p) {
    return (unsigned)__cvta_generic_to_shared(p);
}
__device__ __forceinline__ void mbar_init(unsigned mbar, unsigned count) {
    asm volatile("mbarrier.init.shared.b64 [%0], %1;" :: "r"(mbar), "r"(count) : "memory");
}
__device__ __forceinline__ void mbar_expect_tx(unsigned mbar, unsigned bytes) {
    asm volatile("mbarrier.arrive.expect_tx.shared.b64 _, [%0], %1;" :: "r"(mbar), "r"(bytes) : "memory");
}
__device__ __forceinline__ void mbar_wait0(unsigned mbar) {
    asm volatile(
        "{\n\t"
        ".reg .pred P1;\n\t"
        "WAIT_LOOP_%=:\n\t"
        "mbarrier.try_wait.parity.acquire.cta.shared::cta.b64 P1, [%0], 0, 0x989680;\n\t"
        "@P1 bra.uni WAIT_DONE_%=;\n\t"
        "bra.uni WAIT_LOOP_%=;\n\t"
        "WAIT_DONE_%=:\n\t"
        "}"
        :: "r"(mbar) : "memory");
}
__device__ __forceinline__ void bulk_g2s(unsigned dst, const void* src, unsigned bytes, unsigned mbar) {
    asm volatile("cp.async.bulk.shared::cta.global.mbarrier::complete_tx::bytes [%0], [%1], %2, [%3];"
                 :: "r"(dst), "l"(src), "r"(bytes), "r"(mbar) : "memory");
}

// float4-interleaved transposed weights:  g_sw1T4[((i/4)*256 + h)*4 + (i%4)] = sw1[h][i]
__device__ float g_sw1T4[48 * 256 * 4];
__device__ float g_mw1T4[48 * 256 * 4];
__device__ float g_sw1last[256];          // sw1[h][192]
__device__ float g_sw2T4[64 * 64 * 4];    // [((h/4)*64 + d)*4 + h%4] = sw2[d][h]
__device__ float g_mw2T4[64 * 64 * 4];

// Partial means scratch: 512 half-bn blocks
__device__ float g_ph [512 * 64];
__device__ float g_pp [512 * 64];
__device__ float g_phb[512 * 32];
__device__ float g_pd [512];
__device__ float g_pmg[512];

// mod MLP layer-2 partials: [bn][q][100] (bias folded into q=0; raw, pre-sigmoid)
__device__ float g_l2p[256 * 4 * 100];

// per-nc neuron_id dot products: [nc][hh][c]  (c-minor; shared across the 4 batches)
__device__ float g_ndot_s[64 * 256 * 8];
__device__ float g_ndot_m[64 * 256 * 8];

#define MEANS_BLOCKS 512
#define PREP_BLOCKS  129

// Dynamic smem layout for means blocks (bytes)
#define OFF_H   0
#define OFF_P   32768
#define OFF_B   65536
#define OFF_D   81920
#define OFF_M   82432
#define OFF_BAR 82944
#define OFF_RH  83072
#define OFF_RP  87168
#define OFF_RB  91264
#define SMEM_K1 95360
#define TOTAL_TX (32768u + 32768u + 16384u + 512u + 512u)

// ---------------- K1: TMA-fed partial means (blocks 0..511) + weight repack ----------------
__global__ __launch_bounds__(256)
void means_prep_kernel(const float* __restrict__ h,
                       const float* __restrict__ primitives_state,
                       const float* __restrict__ hebbian_traces,
                       const float* __restrict__ decay_logit,
                       const float* __restrict__ msg_magnitude,
                       const float* __restrict__ sw1,
                       const float* __restrict__ mw1,
                       const float* __restrict__ sw2,
                       const float* __restrict__ mw2)
{
    const int tid = threadIdx.x;

    if (blockIdx.x >= MEANS_BLOCKS) {
        int pt = (blockIdx.x - MEANS_BLOCKS) * 256 + tid;
        if (pt < 12288) {
            int i4 = pt >> 8, hh = pt & 255;
            float4 v = make_float4(sw1[hh * 193 + i4 * 4 + 0], sw1[hh * 193 + i4 * 4 + 1],
                                   sw1[hh * 193 + i4 * 4 + 2], sw1[hh * 193 + i4 * 4 + 3]);
            *(float4*)&g_sw1T4[pt * 4] = v;
        } else if (pt < 24576) {
            int q = pt - 12288, i4 = q >> 8, hh = q & 255;
            float4 v = make_float4(mw1[hh * 192 + i4 * 4 + 0], mw1[hh * 192 + i4 * 4 + 1],
                                   mw1[hh * 192 + i4 * 4 + 2], mw1[hh * 192 + i4 * 4 + 3]);
            *(float4*)&g_mw1T4[q * 4] = v;
        } else if (pt < 28672) {
            int q = pt - 24576, h4 = q >> 6, d = q & 63;
            float4 v = make_float4(sw2[d * 256 + h4 * 4 + 0], sw2[d * 256 + h4 * 4 + 1],
                                   sw2[d * 256 + h4 * 4 + 2], sw2[d * 256 + h4 * 4 + 3]);
            *(float4*)&g_sw2T4[q * 4] = v;
        } else if (pt < 32768) {
            int q = pt - 28672, h4 = q >> 6, d = q & 63;
            float4 v = make_float4(mw2[d * 256 + h4 * 4 + 0], mw2[d * 256 + h4 * 4 + 1],
                                   mw2[d * 256 + h4 * 4 + 2], mw2[d * 256 + h4 * 4 + 3]);
            *(float4*)&g_mw2T4[q * 4] = v;
        } else if (pt < 33024) {
            int hh = pt - 32768;
            g_sw1last[hh] = sw1[hh * 193 + 192];
        }
        return;
    }

    extern __shared__ __align__(16) char smem[];

    const int bn   = blockIdx.x >> 1;
    const int half = blockIdx.x & 1;
    const int c0   = half * 128;
    const int lane = tid & 31;
    const int warp = tid >> 5;
    const int pidx = blockIdx.x;

    const unsigned sbase = smem_u32(smem);
    const unsigned mbar  = sbase + OFF_BAR;

    if (tid == 0) mbar_init(mbar, 1);
    __syncthreads();
    if (tid == 0) {
        mbar_expect_tx(mbar, TOTAL_TX);
        bulk_g2s(sbase + OFF_H, h                + (long)bn * CDIM * DDIM + (long)c0 * DDIM, 32768u, mbar);
        bulk_g2s(sbase + OFF_P, primitives_state + (long)bn * CDIM * DDIM + (long)c0 * DDIM, 32768u, mbar);
        bulk_g2s(sbase + OFF_B, hebbian_traces   + (long)bn * CDIM * KDIM + (long)c0 * KDIM, 16384u, mbar);
        bulk_g2s(sbase + OFF_D, decay_logit      + (long)bn * CDIM + c0, 512u, mbar);
        bulk_g2s(sbase + OFF_M, msg_magnitude    + (long)bn * CDIM + c0, 512u, mbar);
    }
    mbar_wait0(mbar);

    const float4* th4 = (const float4*)(smem + OFF_H);
    const float4* tp4 = (const float4*)(smem + OFF_P);
    const float4* tb4 = (const float4*)(smem + OFF_B);
    float* s_h = (float*)(smem + OFF_RH);
    float* s_p = (float*)(smem + OFF_RP);
    float* s_b = (float*)(smem + OFF_RB);

    const int v16 = tid & 15;
    const int cgr = tid >> 4;
    const int v8  = tid & 7;
    const int cb  = tid >> 3;

    // register reductions from smem tiles
    float4 ha[8], pa[8], ba[4];
    #pragma unroll
    for (int j = 0; j < 8; j++) ha[j] = th4[(cgr + 16 * j) * 16 + v16];
    #pragma unroll
    for (int j = 0; j < 8; j++) pa[j] = tp4[(cgr + 16 * j) * 16 + v16];
    #pragma unroll
    for (int j = 0; j < 4; j++) ba[j] = tb4[(cb + 32 * j) * 8 + v8];

    if (warp == 0) {
        const float* dl = (const float*)(smem + OFF_D);
        float v = dl[lane] + dl[lane + 32] + dl[lane + 64] + dl[lane + 96];
        #pragma unroll
        for (int off = 16; off; off >>= 1) v += __shfl_down_sync(0xffffffffu, v, off);
        if (lane == 0) g_pd[pidx] = v;
    } else if (warp == 1) {
        const float* mg = (const float*)(smem + OFF_M);
        float v = mg[lane] + mg[lane + 32] + mg[lane + 64] + mg[lane + 96];
        #pragma unroll
        for (int off = 16; off; off >>= 1) v += __shfl_down_sync(0xffffffffu, v, off);
        if (lane == 0) g_pmg[pidx] = v;
    }

    float4 hs, ps, bs;
    hs.x = ((ha[0].x + ha[1].x) + (ha[2].x + ha[3].x)) + ((ha[4].x + ha[5].x) + (ha[6].x + ha[7].x));
    hs.y = ((ha[0].y + ha[1].y) + (ha[2].y + ha[3].y)) + ((ha[4].y + ha[5].y) + (ha[6].y + ha[7].y));
    hs.z = ((ha[0].z + ha[1].z) + (ha[2].z + ha[3].z)) + ((ha[4].z + ha[5].z) + (ha[6].z + ha[7].z));
    hs.w = ((ha[0].w + ha[1].w) + (ha[2].w + ha[3].w)) + ((ha[4].w + ha[5].w) + (ha[6].w + ha[7].w));
    ps.x = ((pa[0].x + pa[1].x) + (pa[2].x + pa[3].x)) + ((pa[4].x + pa[5].x) + (pa[6].x + pa[7].x));
    ps.y = ((pa[0].y + pa[1].y) + (pa[2].y + pa[3].y)) + ((pa[4].y + pa[5].y) + (pa[6].y + pa[7].y));
    ps.z = ((pa[0].z + pa[1].z) + (pa[2].z + pa[3].z)) + ((pa[4].z + pa[5].z) + (pa[6].z + pa[7].z));
    ps.w = ((pa[0].w + pa[1].w) + (pa[2].w + pa[3].w)) + ((pa[4].w + pa[5].w) + (pa[6].w + pa[7].w));
    bs.x = (ba[0].x + ba[1].x) + (ba[2].x + ba[3].x);
    bs.y = (ba[0].y + ba[1].y) + (ba[2].y + ba[3].y);
    bs.z = (ba[0].z + ba[1].z) + (ba[2].z + ba[3].z);
    bs.w = (ba[0].w + ba[1].w) + (ba[2].w + ba[3].w);

    *(float4*)&s_h[cgr * 64 + v16 * 4] = hs;
    *(float4*)&s_p[cgr * 64 + v16 * 4] = ps;
    *(float4*)&s_b[cb * 32 + v8 * 4]   = bs;
    __syncthreads();

    if (tid < 64) {
        float t = 0.f;
        #pragma unroll
        for (int g = 0; g < 16; g++) t += s_h[g * 64 + tid];
        g_ph[pidx * 64 + tid] = t;
    } else if (tid < 128) {
        int d = tid - 64;
        float t = 0.f;
        #pragma unroll
        for (int g = 0; g < 16; g++) t += s_p[g * 64 + d];
        g_pp[pidx * 64 + d] = t;
    } else if (tid < 160) {
        int k = tid - 128;
        float t = 0.f;
        #pragma unroll
        for (int c2 = 0; c2 < 32; c2++) t += s_b[c2 * 32 + k];
        g_phb[pidx * 32 + k] = t;
    }
}

// ---------------- K2: mod MLP + neuron_id dot precompute; grid 256 = (nc x 4 quarters) ----------------
__global__ __launch_bounds__(256)
void modmlp_kernel(const float* __restrict__ mod_w1,
                   const float* __restrict__ mod_b1,
                   const float* __restrict__ mod_w2,
                   const float* __restrict__ mod_b2,
                   const float* __restrict__ neuron_id)
{
    __shared__ float s_min[4][232];
    __shared__ float s_hid[4][64];
    __shared__ float s_mm[4];
    __shared__ __align__(16) float s_nid[8][64];
    __shared__ float s_ps[4][512];
    __shared__ float s_pm[4][512];

    const int tid  = threadIdx.x;
    const int warp = tid >> 5;
    const int lane = tid & 31;
    const int nc   = blockIdx.x & 63;
    const int q    = blockIdx.x >> 6;
    const float inv = 1.0f / CDIM;

    {
        int c = tid >> 5, d0 = (tid & 31) * 2;
        *(float2*)&s_nid[c][d0] = *(const float2*)&neuron_id[((long)nc * CDIM + (CDIM - ALPHA) + c) * DDIM + d0];
    }

    {
        int b4 = tid >> 6, d = tid & 63;
        int p0 = ((b4 * NCB + nc) << 1);
        s_min[b4][32 + d] = (g_ph[p0 * 64 + d] + g_ph[(p0 + 1) * 64 + d]) * inv;
        s_min[b4][97 + d] = (g_pp[p0 * 64 + d] + g_pp[(p0 + 1) * 64 + d]) * inv;
        if (tid < 128) {
            int b = tid >> 5, k = tid & 31;
            int p = ((b * NCB + nc) << 1);
            s_min[b][k] = (g_phb[p * 32 + k] + g_phb[(p + 1) * 32 + k]) * inv;
        } else if (tid < 132) {
            int b = tid - 128;
            int p = ((b * NCB + nc) << 1);
            s_min[b][96] = (g_pd[p] + g_pd[p + 1]) * inv;
        } else if (tid < 136) {
            int b = tid - 132;
            int p = ((b * NCB + nc) << 1);
            s_mm[b] = (g_pmg[p] + g_pmg[p + 1]) * inv;
        }
    }
    __syncthreads();
    {
        int b4 = tid >> 6, d = tid & 63;
        s_min[b4][161 + d] = s_mm[b4];
    }
    __syncthreads();

    // ---- neuron_id dots for this hh-quarter (c-minor output) ----
    {
        int hhl = tid & 63, ig = tid >> 6;
        int hh = q * 64 + hhl;
        float accs[8], accm[8];
        #pragma unroll
        for (int c = 0; c < 8; c++) { accs[c] = 0.f; accm[c] = 0.f; }
        #pragma unroll
        for (int s = 0; s < 4; s++) {
            int i4 = 32 + ig * 4 + s;
            int i  = (i4 - 32) * 4;
            float4 ws = *(const float4*)&g_sw1T4[(i4 * 256 + hh) * 4];
            float4 wm = *(const float4*)&g_mw1T4[(i4 * 256 + hh) * 4];
            #pragma unroll
            for (int c = 0; c < 8; c++) {
                float4 nv = *(const float4*)&s_nid[c][i];
                accs[c] += nv.x * ws.x + nv.y * ws.y + nv.z * ws.z + nv.w * ws.w;
                accm[c] += nv.x * wm.x + nv.y * wm.y + nv.z * wm.z + nv.w * wm.w;
            }
        }
        #pragma unroll
        for (int c = 0; c < 8; c++) {
            s_ps[ig][hhl * 8 + c] = accs[c];
            s_pm[ig][hhl * 8 + c] = accm[c];
        }
    }
    __syncthreads();
    for (int o = tid; o < 512; o += 256) {
        int hhl = o >> 3;
        int hh = q * 64 + hhl;
        int c = o & 7;
        g_ndot_s[((long)nc * 256 + hh) * 8 + c] = s_ps[0][o] + s_ps[1][o] + s_ps[2][o] + s_ps[3][o];
        g_ndot_m[((long)nc * 256 + hh) * 8 + c] = s_pm[0][o] + s_pm[1][o] + s_pm[2][o] + s_pm[3][o];
    }

    // layer 1
    for (int r = 0; r < 8; r++) {
        int rloc = warp * 8 + r;
        int h0 = q * 64 + rloc;
        const float* row = mod_w1 + ((long)nc * HDIM + h0) * MODI;
        float a0 = 0.f, a1 = 0.f, a2 = 0.f, a3 = 0.f;
        #pragma unroll
        for (int j = 0; j < 7; j++) {
            int i = lane + 32 * j;
            float w = row[i];
            a0 += w * s_min[0][i];
            a1 += w * s_min[1][i];
            a2 += w * s_min[2][i];
            a3 += w * s_min[3][i];
        }
        if (lane == 0) {
            float w = row[224];
            a0 += w * s_min[0][224];
            a1 += w * s_min[1][224];
            a2 += w * s_min[2][224];
            a3 += w * s_min[3][224];
        }
        #pragma unroll
        for (int off = 16; off; off >>= 1) {
            a0 += __shfl_down_sync(0xffffffffu, a0, off);
            a1 += __shfl_down_sync(0xffffffffu, a1, off);
            a2 += __shfl_down_sync(0xffffffffu, a2, off);
            a3 += __shfl_down_sync(0xffffffffu, a3, off);
        }
        if (lane == 0) {
            float bias = mod_b1[nc * HDIM + h0];
            s_hid[0][rloc] = tanhf(a0 + bias);
            s_hid[1][rloc] = tanhf(a1 + bias);
            s_hid[2][rloc] = tanhf(a2 + bias);
            s_hid[3][rloc] = tanhf(a3 + bias);
        }
    }
    __syncthreads();

    // layer 2 partial
    for (int task = tid; task < 4 * MODO; task += 256) {
        int o = task >> 2, b = task & 3;
        const float* w2c = mod_w2 + (long)nc * HDIM * MODO + (long)(q * 64) * MODO + o;
        float a = 0.f;
        #pragma unroll 8
        for (int hh = 0; hh < 64; hh++) a += w2c[hh * MODO] * s_hid[b][hh];
        if (q == 0) a += mod_b2[nc * MODO + o];
        g_l2p[(((long)b * NCB + nc) * 4 + q) * 100 + o] = a;
    }
}

// ---------------- K3: per-cell pipeline (packed f32x2, direct 64-bit pair loads) ----------------
__global__ __launch_bounds__(512, 2)
void cellmem_kernel(
    const float* __restrict__ h,
    const float* __restrict__ prev_messages,
    const float* __restrict__ state_b1,
    const float* __restrict__ state_b2,
    const float* __restrict__ msg_b1,
    const float* __restrict__ msg_b2,
    const int*   __restrict__ conn_indices,
    float* __restrict__ out)
{
    __shared__ float s_wsig[32];
    __shared__ __align__(16) float s_prim[64];
    __shared__ float s_scal[2];
    __shared__ int   s_conn[256];
    __shared__ float s_hv[8][64];
    __shared__ __align__(16) float s_inv2f[2][8][64];
    __shared__ __align__(16) float s_invT[512];    // [d][c] — c-pairs packed
    __shared__ __align__(16) float s_hnewT[512];   // [d][c]
    __shared__ __align__(16) float s_scratch[4096];
    __shared__ __align__(16) float s_t[2048];      // [hh][c]
    __shared__ __align__(16) float s_acc8T[512];   // [d][c]

    const int tid  = threadIdx.x;
    const int warp = tid >> 5;
    const int lane = tid & 31;
    const int b    = blockIdx.x >> 6;
    const int nc   = blockIdx.x & 63;
    const long bn  = (long)b * NCB + nc;

    const float* hp = h             + bn * CDIM * DDIM;
    const float* pm = prev_messages + bn * CDIM * DDIM;

    const int d64 = tid & 63;
    const int c8  = tid >> 6;

    // ---------- P1 ----------
    if (tid < MODO) {
        float v = g_l2p[(bn * 4 + 0) * 100 + tid] + g_l2p[(bn * 4 + 1) * 100 + tid]
                + g_l2p[(bn * 4 + 2) * 100 + tid] + g_l2p[(bn * 4 + 3) * 100 + tid];
        if (tid < KDIM)        s_wsig[tid] = sigm(v);
        else if (tid == KDIM) { s_scal[0] = v; s_scal[1] = sigm(v); }
        else                   s_prim[tid - KDIM - 1] = v;
    }
    if (tid >= 256 && tid < 512) {
        int q = tid - 256;
        int cc = q >> 5, k = q & 31;
        s_conn[q] = conn_indices[((long)nc * CDIM + (CDIM - ALPHA) + cc) * KDIM + k];
    }
    s_hv[c8][d64] = hp[((CDIM - ALPHA) + c8) * DDIM + d64];
    __syncthreads();

    // ---------- P5: gather ----------
    {
        int cc = warp & 7, kh = warp >> 3;
        float ax = 0.f, ay = 0.f;
        #pragma unroll 4
        for (int j = 0; j < 16; j++) {
            int k = kh * 16 + j;
            const float2* p = (const float2*)(pm + (long)s_conn[cc * KDIM + k] * DDIM);
            float w = s_wsig[k];
            float2 v = p[lane];
            ax += w * v.x;
            ay += w * v.y;
        }
        s_inv2f[kh][cc][lane * 2]     = ax;
        s_inv2f[kh][cc][lane * 2 + 1] = ay;
    }
    __syncthreads();
    s_invT[d64 * 8 + c8] = s_inv2f[0][c8][d64] + s_inv2f[1][c8][d64];
    __syncthreads();

    // ---------- P6: state hidden (f32x2, direct pair loads) ----------
    {
        int hh = tid & 255, ih = tid >> 8;
        unsigned long long acc2[4];
        if (ih == 0) {
            const ulonglong2* np = (const ulonglong2*)&g_ndot_s[((long)nc * 256 + hh) * 8];
            ulonglong2 n01 = np[0], n23 = np[1];
            acc2[0] = n01.x; acc2[1] = n01.y; acc2[2] = n23.x; acc2[3] = n23.y;
        } else {
            unsigned long long z = pk(0.f, 0.f);
            acc2[0] = z; acc2[1] = z; acc2[2] = z; acc2[3] = z;
        }
        float pdot = 0.f;
        #pragma unroll
        for (int s = 0; s < 8; s++) {
            int i4 = ih * 8 + s, i = i4 * 4;
            float wa[4], wb[4];
            *(float4*)wa = *(const float4*)&g_sw1T4[(i4 * 256 + hh) * 4];
            *(float4*)wb = *(const float4*)&g_sw1T4[((i4 + 16) * 256 + hh) * 4];
            float4 pv = *(const float4*)&s_prim[i];
            pdot += pv.x * wb[0] + pv.y * wb[1] + pv.z * wb[2] + pv.w * wb[3];
            #pragma unroll
            for (int e = 0; e < 4; e++) {
                unsigned long long w2 = pk(wa[e], wa[e]);
                const ulonglong2* ivp = (const ulonglong2*)&s_invT[(i + e) * 8];
                ulonglong2 p01 = ivp[0], p23 = ivp[1];
                acc2[0] = ffma2u(w2, p01.x, acc2[0]);
                acc2[1] = ffma2u(w2, p01.y, acc2[1]);
                acc2[2] = ffma2u(w2, p23.x, acc2[2]);
                acc2[3] = ffma2u(w2, p23.y, acc2[3]);
            }
        }
        float extra = pdot;
        if (ih == 0) extra += state_b1[hh] + s_scal[0] * g_sw1last[hh];
        unsigned long long ext2 = pk(extra, extra);
        ulonglong2* op = (ulonglong2*)&s_scratch[ih * 2048 + hh * 8];
        op[0] = make_ulonglong2(add2u(acc2[0], ext2), add2u(acc2[1], ext2));
        op[1] = make_ulonglong2(add2u(acc2[2], ext2), add2u(acc2[3], ext2));
        __syncthreads();
        float4 a  = *(const float4*)&s_scratch[hh * 8 + ih * 4];
        float4 bq = *(const float4*)&s_scratch[2048 + hh * 8 + ih * 4];
        *(float4*)&s_t[hh * 8 + ih * 4] =
            make_float4(tanhf(a.x + bq.x), tanhf(a.y + bq.y), tanhf(a.z + bq.z), tanhf(a.w + bq.w));
    }
    __syncthreads();

    // ---------- P7: update + h_new (f32x2) ----------
    {
        int d = tid & 63, hq = tid >> 6;
        unsigned long long z = pk(0.f, 0.f);
        unsigned long long acc2[4] = {z, z, z, z};
        #pragma unroll
        for (int s = 0; s < 8; s++) {
            int h4 = hq * 8 + s, hh = h4 * 4;
            float wa[4];
            *(float4*)wa = *(const float4*)&g_sw2T4[(h4 * 64 + d) * 4];
            #pragma unroll
            for (int e = 0; e < 4; e++) {
                unsigned long long w2 = pk(wa[e], wa[e]);
                const ulonglong2* tp = (const ulonglong2*)&s_t[(hh + e) * 8];
                ulonglong2 p01 = tp[0], p23 = tp[1];
                acc2[0] = ffma2u(w2, p01.x, acc2[0]);
                acc2[1] = ffma2u(w2, p01.y, acc2[1]);
                acc2[2] = ffma2u(w2, p23.x, acc2[2]);
                acc2[3] = ffma2u(w2, p23.y, acc2[3]);
            }
        }
        __syncthreads();   // s_scratch free (P6 consumers done)
        ulonglong2* op = (ulonglong2*)&s_scratch[hq * 512 + d * 8];
        op[0] = make_ulonglong2(acc2[0], acc2[1]);
        op[1] = make_ulonglong2(acc2[2], acc2[3]);
        __syncthreads();
        float a = state_b2[d64];
        #pragma unroll
        for (int q = 0; q < 8; q++) a += s_scratch[q * 512 + d64 * 8 + c8];
        float ds = s_scal[1];
        s_hnewT[d64 * 8 + c8] = ds * s_hv[c8][d64] + (1.f - ds) * tanhf(a);
    }
    __syncthreads();

    // ---------- P8: msg hidden (f32x2) ----------
    {
        int hh = tid & 255, ih = tid >> 8;
        unsigned long long acc2[4];
        if (ih == 0) {
            const ulonglong2* np = (const ulonglong2*)&g_ndot_m[((long)nc * 256 + hh) * 8];
            ulonglong2 n01 = np[0], n23 = np[1];
            acc2[0] = n01.x; acc2[1] = n01.y; acc2[2] = n23.x; acc2[3] = n23.y;
        } else {
            unsigned long long z = pk(0.f, 0.f);
            acc2[0] = z; acc2[1] = z; acc2[2] = z; acc2[3] = z;
        }
        float pdot = 0.f;
        #pragma unroll
        for (int s = 0; s < 8; s++) {
            int i4 = ih * 8 + s, i = i4 * 4;
            float wa[4], wb[4];
            *(float4*)wa = *(const float4*)&g_mw1T4[(i4 * 256 + hh) * 4];
            *(float4*)wb = *(const float4*)&g_mw1T4[((i4 + 16) * 256 + hh) * 4];
            float4 pv = *(const float4*)&s_prim[i];
            pdot += pv.x * wb[0] + pv.y * wb[1] + pv.z * wb[2] + pv.w * wb[3];
            #pragma unroll
            for (int e = 0; e < 4; e++) {
                unsigned long long w2 = pk(wa[e], wa[e]);
                const ulonglong2* ivp = (const ulonglong2*)&s_hnewT[(i + e) * 8];
                ulonglong2 p01 = ivp[0], p23 = ivp[1];
                acc2[0] = ffma2u(w2, p01.x, acc2[0]);
                acc2[1] = ffma2u(w2, p01.y, acc2[1]);
                acc2[2] = ffma2u(w2, p23.x, acc2[2]);
                acc2[3] = ffma2u(w2, p23.y, acc2[3]);
            }
        }
        float extra = pdot;
        if (ih == 0) extra += msg_b1[hh];
        unsigned long long ext2 = pk(extra, extra);
        __syncthreads();   // s_scratch consumers from P7 done
        ulonglong2* op = (ulonglong2*)&s_scratch[ih * 2048 + hh * 8];
        op[0] = make_ulonglong2(add2u(acc2[0], ext2), add2u(acc2[1], ext2));
        op[1] = make_ulonglong2(add2u(acc2[2], ext2), add2u(acc2[3], ext2));
        __syncthreads();
        float4 a  = *(const float4*)&s_scratch[hh * 8 + ih * 4];
        float4 bq = *(const float4*)&s_scratch[2048 + hh * 8 + ih * 4];
        *(float4*)&s_t[hh * 8 + ih * 4] =
            make_float4(tanhf(a.x + bq.x), tanhf(a.y + bq.y), tanhf(a.z + bq.z), tanhf(a.w + bq.w));
    }
    __syncthreads();

    // ---------- P9: msg out + readout (f32x2) ----------
    {
        int d = tid & 63, hq = tid >> 6;
        unsigned long long z = pk(0.f, 0.f);
        unsigned long long acc2[4] = {z, z, z, z};
        #pragma unroll
        for (int s = 0; s < 8; s++) {
            int h4 = hq * 8 + s, hh = h4 * 4;
            float wa[4];
            *(float4*)wa = *(const float4*)&g_mw2T4[(h4 * 64 + d) * 4];
            #pragma unroll
            for (int e = 0; e < 4; e++) {
                unsigned long long w2 = pk(wa[e], wa[e]);
                const ulonglong2* tp = (const ulonglong2*)&s_t[(hh + e) * 8];
                ulonglong2 p01 = tp[0], p23 = tp[1];
                acc2[0] = ffma2u(w2, p01.x, acc2[0]);
                acc2[1] = ffma2u(w2, p01.y, acc2[1]);
                acc2[2] = ffma2u(w2, p23.x, acc2[2]);
                acc2[3] = ffma2u(w2, p23.y, acc2[3]);
            }
        }
        __syncthreads();
        ulonglong2* op = (ulonglong2*)&s_scratch[hq * 512 + d * 8];
        op[0] = make_ulonglong2(acc2[0], acc2[1]);
        op[1] = make_ulonglong2(acc2[2], acc2[3]);
        __syncthreads();
        float a = msg_b2[d64];
        #pragma unroll
        for (int q = 0; q < 8; q++) a += s_scratch[q * 512 + d64 * 8 + c8];
        s_acc8T[d64 * 8 + c8] = tanhf(a);
    }
    __syncthreads();
    if (tid < 64) {
        float4 a0 = *(const float4*)&s_acc8T[tid * 8];
        float4 a1 = *(const float4*)&s_acc8T[tid * 8 + 4];
        out[(long)b * (NCB * DDIM) + nc * DDIM + tid] =
            ((a0.x + a0.y) + (a0.z + a0.w) + (a1.x + a1.y) + (a1.z + a1.w)) * 0.125f;
    }
}

extern "C" void kernel_launch(void* const* d_in, const int* in_sizes, int n_in,
                              void* d_out, int out_size)
{
    const float* h          = (const float*)d_in[0];
    const float* prev_msg   = (const float*)d_in[1];
    const float* decay      = (const float*)d_in[2];
    const float* prim       = (const float*)d_in[3];
    const float* hebb       = (const float*)d_in[4];
    const float* msgmag     = (const float*)d_in[5];
    // d_in[6] = cc_signals : dead (injection hits cells < ALPHA; output reads cells >= C-ALPHA)
    const float* state_w1   = (const float*)d_in[7];
    const float* state_b1   = (const float*)d_in[8];
    const float* state_w2   = (const float*)d_in[9];
    const float* state_b2   = (const float*)d_in[10];
    const float* msg_w1     = (const float*)d_in[11];
    const float* msg_b1     = (const float*)d_in[12];
    const float* msg_w2     = (const float*)d_in[13];
    const float* msg_b2     = (const float*)d_in[14];
    const float* mod_w1     = (const float*)d_in[15];
    const float* mod_b1     = (const float*)d_in[16];
    const float* mod_w2     = (const float*)d_in[17];
    const float* mod_b2     = (const float*)d_in[18];
    const float* neuron_id  = (const float*)d_in[19];
    const int*   conn       = (const int*)d_in[20];
    float* outp             = (float*)d_out;

    static int configured = 0;
    if (!configured) {
        cudaFuncSetAttribute(means_prep_kernel,
                             cudaFuncAttributeMaxDynamicSharedMemorySize, SMEM_K1);
        configured = 1;
    }

    means_prep_kernel<<<MEANS_BLOCKS + PREP_BLOCKS, 256, SMEM_K1>>>(
        h, prim, hebb, decay, msgmag, state_w1, msg_w1, state_w2, msg_w2);
    modmlp_kernel<<<256, 256>>>(mod_w1, mod_b1, mod_w2, mod_b2, neuron_id);
    cellmem_kernel<<<256, 512>>>(h, prev_msg,
                                 state_b1, state_b2, msg_b1, msg_b2,
                                 conn, outp);
}

// round 11
// speedup vs baseline: 1.0787x; 1.0787x over previous
#include <cuda_runtime.h>
#include <math.h>

#define NCB   64
#define CDIM  256
#define DDIM  64
#define KDIM  32
#define ALPHA 8
#define HDIM  256
#define MODI  225   // K + 3D + 1
#define MODO  97    // K + 1 + D

__device__ __forceinline__ float sigm(float x) { return 1.0f / (1.0f + expf(-x)); }

// packed f32x2 helpers (Blackwell fma.rn.f32x2 / add.rn.f32x2 — not emitted by ptxas from C++)
__device__ __forceinline__ unsigned long long pk(float x, float y) {
    unsigned long long u;
    asm("mov.b64 %0, {%1, %2};" : "=l"(u) : "f"(x), "f"(y));
    return u;
}
__device__ __forceinline__ unsigned long long ffma2u(unsigned long long a, unsigned long long b, unsigned long long c) {
    unsigned long long d;
    asm("fma.rn.f32x2 %0, %1, %2, %3;" : "=l"(d) : "l"(a), "l"(b), "l"(c));
    return d;
}
__device__ __forceinline__ unsigned long long add2u(unsigned long long a, unsigned long long b) {
    unsigned long long d;
    asm("add.rn.f32x2 %0, %1, %2;" : "=l"(d) : "l"(a), "l"(b));
    return d;
}

// float4-interleaved transposed weights:  g_sw1T4[((i/4)*256 + h)*4 + (i%4)] = sw1[h][i]
__device__ float g_sw1T4[48 * 256 * 4];
__device__ float g_mw1T4[48 * 256 * 4];
__device__ float g_sw1last[256];          // sw1[h][192]
__device__ float g_sw2T4[64 * 64 * 4];    // [((h/4)*64 + d)*4 + h%4] = sw2[d][h]
__device__ float g_mw2T4[64 * 64 * 4];

// Partial means scratch: 512 half-bn blocks
__device__ float g_ph [512 * 64];
__device__ float g_pp [512 * 64];
__device__ float g_phb[512 * 32];
__device__ float g_pd [512];
__device__ float g_pmg[512];

// mod MLP layer-2 partials: [bn][q][100] (bias folded into q=0; raw, pre-sigmoid)
__device__ float g_l2p[256 * 4 * 100];

// per-nc neuron_id dot products: [nc][hh][c]  (c-minor; shared across the 4 batches)
__device__ float g_ndot_s[64 * 256 * 8];
__device__ float g_ndot_m[64 * 256 * 8];

#define MEANS_BLOCKS 512
#define PREP_BLOCKS  129

// ---------------- K1: partial means (blocks 0..511) + weight repack (512..640) ----------------
__global__ __launch_bounds__(256)
void means_prep_kernel(const float* __restrict__ h,
                       const float* __restrict__ primitives_state,
                       const float* __restrict__ hebbian_traces,
                       const float* __restrict__ decay_logit,
                       const float* __restrict__ msg_magnitude,
                       const float* __restrict__ sw1,
                       const float* __restrict__ mw1,
                       const float* __restrict__ sw2,
                       const float* __restrict__ mw2)
{
    const int tid = threadIdx.x;

    if (blockIdx.x >= MEANS_BLOCKS) {
        int pt = (blockIdx.x - MEANS_BLOCKS) * 256 + tid;
        if (pt < 12288) {
            int i4 = pt >> 8, hh = pt & 255;
            float4 v = make_float4(sw1[hh * 193 + i4 * 4 + 0], sw1[hh * 193 + i4 * 4 + 1],
                                   sw1[hh * 193 + i4 * 4 + 2], sw1[hh * 193 + i4 * 4 + 3]);
            *(float4*)&g_sw1T4[pt * 4] = v;
        } else if (pt < 24576) {
            int q = pt - 12288, i4 = q >> 8, hh = q & 255;
            float4 v = make_float4(mw1[hh * 192 + i4 * 4 + 0], mw1[hh * 192 + i4 * 4 + 1],
                                   mw1[hh * 192 + i4 * 4 + 2], mw1[hh * 192 + i4 * 4 + 3]);
            *(float4*)&g_mw1T4[q * 4] = v;
        } else if (pt < 28672) {
            int q = pt - 24576, h4 = q >> 6, d = q & 63;
            float4 v = make_float4(sw2[d * 256 + h4 * 4 + 0], sw2[d * 256 + h4 * 4 + 1],
                                   sw2[d * 256 + h4 * 4 + 2], sw2[d * 256 + h4 * 4 + 3]);
            *(float4*)&g_sw2T4[q * 4] = v;
        } else if (pt < 32768) {
            int q = pt - 28672, h4 = q >> 6, d = q & 63;
            float4 v = make_float4(mw2[d * 256 + h4 * 4 + 0], mw2[d * 256 + h4 * 4 + 1],
                                   mw2[d * 256 + h4 * 4 + 2], mw2[d * 256 + h4 * 4 + 3]);
            *(float4*)&g_mw2T4[q * 4] = v;
        } else if (pt < 33024) {
            int hh = pt - 32768;
            g_sw1last[hh] = sw1[hh * 193 + 192];
        }
        return;
    }

    __shared__ float s_h[1024];
    __shared__ float s_p[1024];
    __shared__ float s_b[1024];

    const int bn   = blockIdx.x >> 1;
    const int half = blockIdx.x & 1;
    const int c0   = half * 128;
    const int lane = tid & 31;
    const int warp = tid >> 5;
    const int pidx = blockIdx.x;

    const float4* hp4 = (const float4*)(h                + (long)bn * CDIM * DDIM + (long)c0 * DDIM);
    const float4* pp4 = (const float4*)(primitives_state + (long)bn * CDIM * DDIM + (long)c0 * DDIM);
    const float4* hb4 = (const float4*)(hebbian_traces   + (long)bn * CDIM * KDIM + (long)c0 * KDIM);

    const int v16 = tid & 15;
    const int cgr = tid >> 4;
    const int v8  = tid & 7;
    const int cb  = tid >> 3;

    // Issue ALL loads up front (20 independent LDG.128 per thread)
    float4 ha[8], pa[8], ba[4];
    #pragma unroll
    for (int j = 0; j < 8; j++) ha[j] = hp4[(cgr + 16 * j) * 16 + v16];
    #pragma unroll
    for (int j = 0; j < 8; j++) pa[j] = pp4[(cgr + 16 * j) * 16 + v16];
    #pragma unroll
    for (int j = 0; j < 4; j++) ba[j] = hb4[(cb + 32 * j) * 8 + v8];

    if (warp == 0) {
        const float* dl = decay_logit + (long)bn * CDIM + c0;
        float v = dl[lane] + dl[lane + 32] + dl[lane + 64] + dl[lane + 96];
        #pragma unroll
        for (int off = 16; off; off >>= 1) v += __shfl_down_sync(0xffffffffu, v, off);
        if (lane == 0) g_pd[pidx] = v;
    } else if (warp == 1) {
        const float* mg = msg_magnitude + (long)bn * CDIM + c0;
        float v = mg[lane] + mg[lane + 32] + mg[lane + 64] + mg[lane + 96];
        #pragma unroll
        for (int off = 16; off; off >>= 1) v += __shfl_down_sync(0xffffffffu, v, off);
        if (lane == 0) g_pmg[pidx] = v;
    }

    float4 hs, ps, bs;
    hs.x = ((ha[0].x + ha[1].x) + (ha[2].x + ha[3].x)) + ((ha[4].x + ha[5].x) + (ha[6].x + ha[7].x));
    hs.y = ((ha[0].y + ha[1].y) + (ha[2].y + ha[3].y)) + ((ha[4].y + ha[5].y) + (ha[6].y + ha[7].y));
    hs.z = ((ha[0].z + ha[1].z) + (ha[2].z + ha[3].z)) + ((ha[4].z + ha[5].z) + (ha[6].z + ha[7].z));
    hs.w = ((ha[0].w + ha[1].w) + (ha[2].w + ha[3].w)) + ((ha[4].w + ha[5].w) + (ha[6].w + ha[7].w));
    ps.x = ((pa[0].x + pa[1].x) + (pa[2].x + pa[3].x)) + ((pa[4].x + pa[5].x) + (pa[6].x + pa[7].x));
    ps.y = ((pa[0].y + pa[1].y) + (pa[2].y + pa[3].y)) + ((pa[4].y + pa[5].y) + (pa[6].y + pa[7].y));
    ps.z = ((pa[0].z + pa[1].z) + (pa[2].z + pa[3].z)) + ((pa[4].z + pa[5].z) + (pa[6].z + pa[7].z));
    ps.w = ((pa[0].w + pa[1].w) + (pa[2].w + pa[3].w)) + ((pa[4].w + pa[5].w) + (pa[6].w + pa[7].w));
    bs.x = (ba[0].x + ba[1].x) + (ba[2].x + ba[3].x);
    bs.y = (ba[0].y + ba[1].y) + (ba[2].y + ba[3].y);
    bs.z = (ba[0].z + ba[1].z) + (ba[2].z + ba[3].z);
    bs.w = (ba[0].w + ba[1].w) + (ba[2].w + ba[3].w);

    *(float4*)&s_h[cgr * 64 + v16 * 4] = hs;
    *(float4*)&s_p[cgr * 64 + v16 * 4] = ps;
    *(float4*)&s_b[cb * 32 + v8 * 4]   = bs;
    __syncthreads();

    if (tid < 64) {
        float t = 0.f;
        #pragma unroll
        for (int g = 0; g < 16; g++) t += s_h[g * 64 + tid];
        g_ph[pidx * 64 + tid] = t;
    } else if (tid < 128) {
        int d = tid - 64;
        float t = 0.f;
        #pragma unroll
        for (int g = 0; g < 16; g++) t += s_p[g * 64 + d];
        g_pp[pidx * 64 + d] = t;
    } else if (tid < 160) {
        int k = tid - 128;
        float t = 0.f;
        #pragma unroll
        for (int c2 = 0; c2 < 32; c2++) t += s_b[c2 * 32 + k];
        g_phb[pidx * 32 + k] = t;
    }
}

// ---------------- K2: mod MLP; grid 512 = (nc x 4 quarters x 2 batch-pairs) ----------------
__global__ __launch_bounds__(256)
void modmlp_kernel(const float* __restrict__ mod_w1,
                   const float* __restrict__ mod_b1,
                   const float* __restrict__ mod_w2,
                   const float* __restrict__ mod_b2,
                   const float* __restrict__ neuron_id)
{
    __shared__ float s_min[2][232];
    __shared__ float s_hid[2][64];
    __shared__ float s_mm[2];
    __shared__ __align__(16) float s_nid[8][64];
    __shared__ float s_ps[4][512];
    __shared__ float s_pm[4][512];

    const int tid  = threadIdx.x;
    const int warp = tid >> 5;
    const int lane = tid & 31;
    const int nc   = blockIdx.x & 63;
    const int q    = (blockIdx.x >> 6) & 3;
    const int bp   = blockIdx.x >> 8;     // 0..1 (batch pair)
    const float inv = 1.0f / CDIM;

    if (bp == 0) {
        int c = tid >> 5, d0 = (tid & 31) * 2;
        *(float2*)&s_nid[c][d0] = *(const float2*)&neuron_id[((long)nc * CDIM + (CDIM - ALPHA) + c) * DDIM + d0];
    }

    // assemble mod_in for this block's 2 batches
    {
        int b2 = tid >> 7, r = tid & 127;
        int b  = bp * 2 + b2;
        int p0 = ((b * NCB + nc) << 1);
        if (r < 64) {
            s_min[b2][32 + r] = (g_ph[p0 * 64 + r] + g_ph[(p0 + 1) * 64 + r]) * inv;
        } else {
            int d = r - 64;
            s_min[b2][97 + d] = (g_pp[p0 * 64 + d] + g_pp[(p0 + 1) * 64 + d]) * inv;
        }
        if (tid < 64) {
            int bb = tid >> 5, k = tid & 31;
            int p = (((bp * 2 + bb) * NCB + nc) << 1);
            s_min[bb][k] = (g_phb[p * 32 + k] + g_phb[(p + 1) * 32 + k]) * inv;
        } else if (tid < 66) {
            int bb = tid - 64;
            int p = (((bp * 2 + bb) * NCB + nc) << 1);
            s_min[bb][96] = (g_pd[p] + g_pd[p + 1]) * inv;
        } else if (tid < 68) {
            int bb = tid - 66;
            int p = (((bp * 2 + bb) * NCB + nc) << 1);
            s_mm[bb] = (g_pmg[p] + g_pmg[p + 1]) * inv;
        }
    }
    __syncthreads();
    {
        int b2 = tid >> 7, r = tid & 127;
        if (r < 64) s_min[b2][161 + r] = s_mm[b2];
    }
    __syncthreads();

    // ---- neuron_id dots for this hh-quarter (bp==0 blocks only; c-minor output) ----
    if (bp == 0) {
        int hhl = tid & 63, ig = tid >> 6;
        int hh = q * 64 + hhl;
        float accs[8], accm[8];
        #pragma unroll
        for (int c = 0; c < 8; c++) { accs[c] = 0.f; accm[c] = 0.f; }
        #pragma unroll
        for (int s = 0; s < 4; s++) {
            int i4 = 32 + ig * 4 + s;
            int i  = (i4 - 32) * 4;
            float4 ws = *(const float4*)&g_sw1T4[(i4 * 256 + hh) * 4];
            float4 wm = *(const float4*)&g_mw1T4[(i4 * 256 + hh) * 4];
            #pragma unroll
            for (int c = 0; c < 8; c++) {
                float4 nv = *(const float4*)&s_nid[c][i];
                accs[c] += nv.x * ws.x + nv.y * ws.y + nv.z * ws.z + nv.w * ws.w;
                accm[c] += nv.x * wm.x + nv.y * wm.y + nv.z * wm.z + nv.w * wm.w;
            }
        }
        #pragma unroll
        for (int c = 0; c < 8; c++) {
            s_ps[ig][hhl * 8 + c] = accs[c];
            s_pm[ig][hhl * 8 + c] = accm[c];
        }
        __syncthreads();
        for (int o = tid; o < 512; o += 256) {
            int hhl2 = o >> 3;
            int hh2 = q * 64 + hhl2;
            int c = o & 7;
            g_ndot_s[((long)nc * 256 + hh2) * 8 + c] = s_ps[0][o] + s_ps[1][o] + s_ps[2][o] + s_ps[3][o];
            g_ndot_m[((long)nc * 256 + hh2) * 8 + c] = s_pm[0][o] + s_pm[1][o] + s_pm[2][o] + s_pm[3][o];
        }
    }

    // layer 1: 64 rows (this quarter), warp-per-row, 2 batches per weight read
    for (int r = 0; r < 8; r++) {
        int rloc = warp * 8 + r;
        int h0 = q * 64 + rloc;
        const float* row = mod_w1 + ((long)nc * HDIM + h0) * MODI;
        float a0 = 0.f, a1 = 0.f;
        #pragma unroll
        for (int j = 0; j < 7; j++) {
            int i = lane + 32 * j;
            float w = row[i];
            a0 += w * s_min[0][i];
            a1 += w * s_min[1][i];
        }
        if (lane == 0) {
            float w = row[224];
            a0 += w * s_min[0][224];
            a1 += w * s_min[1][224];
        }
        #pragma unroll
        for (int off = 16; off; off >>= 1) {
            a0 += __shfl_down_sync(0xffffffffu, a0, off);
            a1 += __shfl_down_sync(0xffffffffu, a1, off);
        }
        if (lane == 0) {
            float bias = mod_b1[nc * HDIM + h0];
            s_hid[0][rloc] = tanhf(a0 + bias);
            s_hid[1][rloc] = tanhf(a1 + bias);
        }
    }
    __syncthreads();

    // layer 2 partial over this quarter's 64 hidden units (2 batches)
    if (tid < 194) {
        int o = tid >> 1, bl = tid & 1;
        int b = bp * 2 + bl;
        const float* w2c = mod_w2 + (long)nc * HDIM * MODO + (long)(q * 64) * MODO + o;
        float a = 0.f;
        #pragma unroll 8
        for (int hh = 0; hh < 64; hh++) a += w2c[hh * MODO] * s_hid[bl][hh];
        if (q == 0) a += mod_b2[nc * MODO + o];
        g_l2p[(((long)b * NCB + nc) * 4 + q) * 100 + o] = a;
    }
}

// ---------------- K3: per-cell pipeline (packed f32x2, direct 64-bit pair loads) ----------------
__global__ __launch_bounds__(512, 2)
void cellmem_kernel(
    const float* __restrict__ h,
    const float* __restrict__ prev_messages,
    const float* __restrict__ state_b1,
    const float* __restrict__ state_b2,
    const float* __restrict__ msg_b1,
    const float* __restrict__ msg_b2,
    const int*   __restrict__ conn_indices,
    float* __restrict__ out)
{
    __shared__ float s_wsig[32];
    __shared__ __align__(16) float s_prim[64];
    __shared__ float s_scal[2];
    __shared__ int   s_conn[256];
    __shared__ float s_hv[8][64];
    __shared__ __align__(16) float s_inv2f[2][8][64];
    __shared__ __align__(16) float s_invT[512];    // [d][c] — c-pairs packed
    __shared__ __align__(16) float s_hnewT[512];   // [d][c]
    __shared__ __align__(16) float s_scratch[4096];
    __shared__ __align__(16) float s_t[2048];      // [hh][c]
    __shared__ __align__(16) float s_acc8T[512];   // [d][c]

    const int tid  = threadIdx.x;
    const int warp = tid >> 5;
    const int lane = tid & 31;
    const int b    = blockIdx.x >> 6;
    const int nc   = blockIdx.x & 63;
    const long bn  = (long)b * NCB + nc;

    const float* hp = h             + bn * CDIM * DDIM;
    const float* pm = prev_messages + bn * CDIM * DDIM;

    const int d64 = tid & 63;
    const int c8  = tid >> 6;

    // ---------- P1 ----------
    if (tid < MODO) {
        float v = g_l2p[(bn * 4 + 0) * 100 + tid] + g_l2p[(bn * 4 + 1) * 100 + tid]
                + g_l2p[(bn * 4 + 2) * 100 + tid] + g_l2p[(bn * 4 + 3) * 100 + tid];
        if (tid < KDIM)        s_wsig[tid] = sigm(v);
        else if (tid == KDIM) { s_scal[0] = v; s_scal[1] = sigm(v); }
        else                   s_prim[tid - KDIM - 1] = v;
    }
    if (tid >= 256 && tid < 512) {
        int q = tid - 256;
        int cc = q >> 5, k = q & 31;
        s_conn[q] = conn_indices[((long)nc * CDIM + (CDIM - ALPHA) + cc) * KDIM + k];
    }
    s_hv[c8][d64] = hp[((CDIM - ALPHA) + c8) * DDIM + d64];
    __syncthreads();

    // ---------- P5: gather ----------
    {
        int cc = warp & 7, kh = warp >> 3;
        float ax = 0.f, ay = 0.f;
        #pragma unroll 4
        for (int j = 0; j < 16; j++) {
            int k = kh * 16 + j;
            const float2* p = (const float2*)(pm + (long)s_conn[cc * KDIM + k] * DDIM);
            float w = s_wsig[k];
            float2 v = p[lane];
            ax += w * v.x;
            ay += w * v.y;
        }
        s_inv2f[kh][cc][lane * 2]     = ax;
        s_inv2f[kh][cc][lane * 2 + 1] = ay;
    }
    __syncthreads();
    s_invT[d64 * 8 + c8] = s_inv2f[0][c8][d64] + s_inv2f[1][c8][d64];
    __syncthreads();

    // ---------- P6: state hidden (f32x2, direct pair loads) ----------
    {
        int hh = tid & 255, ih = tid >> 8;
        unsigned long long acc2[4];
        if (ih == 0) {
            const ulonglong2* np = (const ulonglong2*)&g_ndot_s[((long)nc * 256 + hh) * 8];
            ulonglong2 n01 = np[0], n23 = np[1];
            acc2[0] = n01.x; acc2[1] = n01.y; acc2[2] = n23.x; acc2[3] = n23.y;
        } else {
            unsigned long long z = pk(0.f, 0.f);
            acc2[0] = z; acc2[1] = z; acc2[2] = z; acc2[3] = z;
        }
        float pdot = 0.f;
        #pragma unroll
        for (int s = 0; s < 8; s++) {
            int i4 = ih * 8 + s, i = i4 * 4;
            float wa[4], wb[4];
            *(float4*)wa = *(const float4*)&g_sw1T4[(i4 * 256 + hh) * 4];
            *(float4*)wb = *(const float4*)&g_sw1T4[((i4 + 16) * 256 + hh) * 4];
            float4 pv = *(const float4*)&s_prim[i];
            pdot += pv.x * wb[0] + pv.y * wb[1] + pv.z * wb[2] + pv.w * wb[3];
            #pragma unroll
            for (int e = 0; e < 4; e++) {
                unsigned long long w2 = pk(wa[e], wa[e]);
                const ulonglong2* ivp = (const ulonglong2*)&s_invT[(i + e) * 8];
                ulonglong2 p01 = ivp[0], p23 = ivp[1];
                acc2[0] = ffma2u(w2, p01.x, acc2[0]);
                acc2[1] = ffma2u(w2, p01.y, acc2[1]);
                acc2[2] = ffma2u(w2, p23.x, acc2[2]);
                acc2[3] = ffma2u(w2, p23.y, acc2[3]);
            }
        }
        float extra = pdot;
        if (ih == 0) extra += state_b1[hh] + s_scal[0] * g_sw1last[hh];
        unsigned long long ext2 = pk(extra, extra);
        ulonglong2* op = (ulonglong2*)&s_scratch[ih * 2048 + hh * 8];
        op[0] = make_ulonglong2(add2u(acc2[0], ext2), add2u(acc2[1], ext2));
        op[1] = make_ulonglong2(add2u(acc2[2], ext2), add2u(acc2[3], ext2));
        __syncthreads();
        float4 a  = *(const float4*)&s_scratch[hh * 8 + ih * 4];
        float4 bq = *(const float4*)&s_scratch[2048 + hh * 8 + ih * 4];
        *(float4*)&s_t[hh * 8 + ih * 4] =
            make_float4(tanhf(a.x + bq.x), tanhf(a.y + bq.y), tanhf(a.z + bq.z), tanhf(a.w + bq.w));
    }
    __syncthreads();

    // ---------- P7: update + h_new (f32x2) ----------
    {
        int d = tid & 63, hq = tid >> 6;
        unsigned long long z = pk(0.f, 0.f);
        unsigned long long acc2[4] = {z, z, z, z};
        #pragma unroll
        for (int s = 0; s < 8; s++) {
            int h4 = hq * 8 + s, hh = h4 * 4;
            float wa[4];
            *(float4*)wa = *(const float4*)&g_sw2T4[(h4 * 64 + d) * 4];
            #pragma unroll
            for (int e = 0; e < 4; e++) {
                unsigned long long w2 = pk(wa[e], wa[e]);
                const ulonglong2* tp = (const ulonglong2*)&s_t[(hh + e) * 8];
                ulonglong2 p01 = tp[0], p23 = tp[1];
                acc2[0] = ffma2u(w2, p01.x, acc2[0]);
                acc2[1] = ffma2u(w2, p01.y, acc2[1]);
                acc2[2] = ffma2u(w2, p23.x, acc2[2]);
                acc2[3] = ffma2u(w2, p23.y, acc2[3]);
            }
        }
        __syncthreads();   // s_scratch free (P6 consumers done)
        ulonglong2* op = (ulonglong2*)&s_scratch[hq * 512 + d * 8];
        op[0] = make_ulonglong2(acc2[0], acc2[1]);
        op[1] = make_ulonglong2(acc2[2], acc2[3]);
        __syncthreads();
        float a = state_b2[d64];
        #pragma unroll
        for (int q = 0; q < 8; q++) a += s_scratch[q * 512 + d64 * 8 + c8];
        float ds = s_scal[1];
        s_hnewT[d64 * 8 + c8] = ds * s_hv[c8][d64] + (1.f - ds) * tanhf(a);
    }
    __syncthreads();

    // ---------- P8: msg hidden (f32x2) ----------
    {
        int hh = tid & 255, ih = tid >> 8;
        unsigned long long acc2[4];
        if (ih == 0) {
            const ulonglong2* np = (const ulonglong2*)&g_ndot_m[((long)nc * 256 + hh) * 8];
            ulonglong2 n01 = np[0], n23 = np[1];
            acc2[0] = n01.x; acc2[1] = n01.y; acc2[2] = n23.x; acc2[3] = n23.y;
        } else {
            unsigned long long z = pk(0.f, 0.f);
            acc2[0] = z; acc2[1] = z; acc2[2] = z; acc2[3] = z;
        }
        float pdot = 0.f;
        #pragma unroll
        for (int s = 0; s < 8; s++) {
            int i4 = ih * 8 + s, i = i4 * 4;
            float wa[4], wb[4];
            *(float4*)wa = *(const float4*)&g_mw1T4[(i4 * 256 + hh) * 4];
            *(float4*)wb = *(const float4*)&g_mw1T4[((i4 + 16) * 256 + hh) * 4];
            float4 pv = *(const float4*)&s_prim[i];
            pdot += pv.x * wb[0] + pv.y * wb[1] + pv.z * wb[2] + pv.w * wb[3];
            #pragma unroll
            for (int e = 0; e < 4; e++) {
                unsigned long long w2 = pk(wa[e], wa[e]);
                const ulonglong2* ivp = (const ulonglong2*)&s_hnewT[(i + e) * 8];
                ulonglong2 p01 = ivp[0], p23 = ivp[1];
                acc2[0] = ffma2u(w2, p01.x, acc2[0]);
                acc2[1] = ffma2u(w2, p01.y, acc2[1]);
                acc2[2] = ffma2u(w2, p23.x, acc2[2]);
                acc2[3] = ffma2u(w2, p23.y, acc2[3]);
            }
        }
        float extra = pdot;
        if (ih == 0) extra += msg_b1[hh];
        unsigned long long ext2 = pk(extra, extra);
        __syncthreads();   // s_scratch consumers from P7 done
        ulonglong2* op = (ulonglong2*)&s_scratch[ih * 2048 + hh * 8];
        op[0] = make_ulonglong2(add2u(acc2[0], ext2), add2u(acc2[1], ext2));
        op[1] = make_ulonglong2(add2u(acc2[2], ext2), add2u(acc2[3], ext2));
        __syncthreads();
        float4 a  = *(const float4*)&s_scratch[hh * 8 + ih * 4];
        float4 bq = *(const float4*)&s_scratch[2048 + hh * 8 + ih * 4];
        *(float4*)&s_t[hh * 8 + ih * 4] =
            make_float4(tanhf(a.x + bq.x), tanhf(a.y + bq.y), tanhf(a.z + bq.z), tanhf(a.w + bq.w));
    }
    __syncthreads();

    // ---------- P9: msg out + readout (f32x2) ----------
    {
        int d = tid & 63, hq = tid >> 6;
        unsigned long long z = pk(0.f, 0.f);
        unsigned long long acc2[4] = {z, z, z, z};
        #pragma unroll
        for (int s = 0; s < 8; s++) {
            int h4 = hq * 8 + s, hh = h4 * 4;
            float wa[4];
            *(float4*)wa = *(const float4*)&g_mw2T4[(h4 * 64 + d) * 4];
            #pragma unroll
            for (int e = 0; e < 4; e++) {
                unsigned long long w2 = pk(wa[e], wa[e]);
                const ulonglong2* tp = (const ulonglong2*)&s_t[(hh + e) * 8];
                ulonglong2 p01 = tp[0], p23 = tp[1];
                acc2[0] = ffma2u(w2, p01.x, acc2[0]);
                acc2[1] = ffma2u(w2, p01.y, acc2[1]);
                acc2[2] = ffma2u(w2, p23.x, acc2[2]);
                acc2[3] = ffma2u(w2, p23.y, acc2[3]);
            }
        }
        __syncthreads();
        ulonglong2* op = (ulonglong2*)&s_scratch[hq * 512 + d * 8];
        op[0] = make_ulonglong2(acc2[0], acc2[1]);
        op[1] = make_ulonglong2(acc2[2], acc2[3]);
        __syncthreads();
        float a = msg_b2[d64];
        #pragma unroll
        for (int q = 0; q < 8; q++) a += s_scratch[q * 512 + d64 * 8 + c8];
        s_acc8T[d64 * 8 + c8] = tanhf(a);
    }
    __syncthreads();
    if (tid < 64) {
        float4 a0 = *(const float4*)&s_acc8T[tid * 8];
        float4 a1 = *(const float4*)&s_acc8T[tid * 8 + 4];
        out[(long)b * (NCB * DDIM) + nc * DDIM + tid] =
            ((a0.x + a0.y) + (a0.z + a0.w) + (a1.x + a1.y) + (a1.z + a1.w)) * 0.125f;
    }
}

extern "C" void kernel_launch(void* const* d_in, const int* in_sizes, int n_in,
                              void* d_out, int out_size)
{
    const float* h          = (const float*)d_in[0];
    const float* prev_msg   = (const float*)d_in[1];
    const float* decay      = (const float*)d_in[2];
    const float* prim       = (const float*)d_in[3];
    const float* hebb       = (const float*)d_in[4];
    const float* msgmag     = (const float*)d_in[5];
    // d_in[6] = cc_signals : dead (injection hits cells < ALPHA; output reads cells >= C-ALPHA)
    const float* state_w1   = (const float*)d_in[7];
    const float* state_b1   = (const float*)d_in[8];
    const float* state_w2   = (const float*)d_in[9];
    const float* state_b2   = (const float*)d_in[10];
    const float* msg_w1     = (const float*)d_in[11];
    const float* msg_b1     = (const float*)d_in[12];
    const float* msg_w2     = (const float*)d_in[13];
    const float* msg_b2     = (const float*)d_in[14];
    const float* mod_w1     = (const float*)d_in[15];
    const float* mod_b1     = (const float*)d_in[16];
    const float* mod_w2     = (const float*)d_in[17];
    const float* mod_b2     = (const float*)d_in[18];
    const float* neuron_id  = (const float*)d_in[19];
    const int*   conn       = (const int*)d_in[20];
    float* outp             = (float*)d_out;

    means_prep_kernel<<<MEANS_BLOCKS + PREP_BLOCKS, 256>>>(
        h, prim, hebb, decay, msgmag, state_w1, msg_w1, state_w2, msg_w2);
    modmlp_kernel<<<512, 256>>>(mod_w1, mod_b1, mod_w2, mod_b2, neuron_id);
    cellmem_kernel<<<256, 512>>>(h, prev_msg,
                                 state_b1, state_b2, msg_b1, msg_b2,
                                 conn, outp);
}

// round 12
// speedup vs baseline: 1.0819x; 1.0029x over previous
#include <cuda_runtime.h>
#include <math.h>

#define NCB   64
#define CDIM  256
#define DDIM  64
#define KDIM  32
#define ALPHA 8
#define HDIM  256
#define MODI  225   // K + 3D + 1
#define MODO  97    // K + 1 + D

__device__ __forceinline__ float sigm(float x) { return 1.0f / (1.0f + expf(-x)); }

// packed f32x2 helpers (Blackwell fma.rn.f32x2 / add.rn.f32x2 — not emitted by ptxas from C++)
__device__ __forceinline__ unsigned long long pk(float x, float y) {
    unsigned long long u;
    asm("mov.b64 %0, {%1, %2};" : "=l"(u) : "f"(x), "f"(y));
    return u;
}
__device__ __forceinline__ unsigned long long ffma2u(unsigned long long a, unsigned long long b, unsigned long long c) {
    unsigned long long d;
    asm("fma.rn.f32x2 %0, %1, %2, %3;" : "=l"(d) : "l"(a), "l"(b), "l"(c));
    return d;
}
__device__ __forceinline__ unsigned long long add2u(unsigned long long a, unsigned long long b) {
    unsigned long long d;
    asm("add.rn.f32x2 %0, %1, %2;" : "=l"(d) : "l"(a), "l"(b));
    return d;
}

// float4-interleaved transposed weights:  g_sw1T4[((i/4)*256 + h)*4 + (i%4)] = sw1[h][i]
__device__ float g_sw1T4[48 * 256 * 4];
__device__ float g_mw1T4[48 * 256 * 4];
__device__ float g_sw1last[256];          // sw1[h][192]
__device__ float g_sw2T4[64 * 64 * 4];    // [((h/4)*64 + d)*4 + h%4] = sw2[d][h]
__device__ float g_mw2T4[64 * 64 * 4];

// Partial means scratch: 512 half-bn blocks
__device__ float g_ph [512 * 64];
__device__ float g_pp [512 * 64];
__device__ float g_phb[512 * 32];
__device__ float g_pd [512];
__device__ float g_pmg[512];

// mod MLP layer-2 partials: [bn][q][100] (bias folded into q=0; raw, pre-sigmoid)
__device__ float g_l2p[256 * 4 * 100];

// per-nc neuron_id dot products: [nc][hh][c]  (c-minor; shared across the 4 batches)
__device__ float g_ndot_s[64 * 256 * 8];
__device__ float g_ndot_m[64 * 256 * 8];

#define MEANS_BLOCKS 512
#define PREP_BLOCKS  129

// ---------------- K1: partial means (blocks 0..511) + weight repack (512..640) ----------------
__global__ __launch_bounds__(256)
void means_prep_kernel(const float* __restrict__ h,
                       const float* __restrict__ primitives_state,
                       const float* __restrict__ hebbian_traces,
                       const float* __restrict__ decay_logit,
                       const float* __restrict__ msg_magnitude,
                       const float* __restrict__ sw1,
                       const float* __restrict__ mw1,
                       const float* __restrict__ sw2,
                       const float* __restrict__ mw2)
{
    const int tid = threadIdx.x;

    if (blockIdx.x >= MEANS_BLOCKS) {
        int pt = (blockIdx.x - MEANS_BLOCKS) * 256 + tid;
        if (pt < 12288) {
            int i4 = pt >> 8, hh = pt & 255;
            float4 v = make_float4(sw1[hh * 193 + i4 * 4 + 0], sw1[hh * 193 + i4 * 4 + 1],
                                   sw1[hh * 193 + i4 * 4 + 2], sw1[hh * 193 + i4 * 4 + 3]);
            *(float4*)&g_sw1T4[pt * 4] = v;
        } else if (pt < 24576) {
            int q = pt - 12288, i4 = q >> 8, hh = q & 255;
            float4 v = make_float4(mw1[hh * 192 + i4 * 4 + 0], mw1[hh * 192 + i4 * 4 + 1],
                                   mw1[hh * 192 + i4 * 4 + 2], mw1[hh * 192 + i4 * 4 + 3]);
            *(float4*)&g_mw1T4[q * 4] = v;
        } else if (pt < 28672) {
            int q = pt - 24576, h4 = q >> 6, d = q & 63;
            float4 v = make_float4(sw2[d * 256 + h4 * 4 + 0], sw2[d * 256 + h4 * 4 + 1],
                                   sw2[d * 256 + h4 * 4 + 2], sw2[d * 256 + h4 * 4 + 3]);
            *(float4*)&g_sw2T4[q * 4] = v;
        } else if (pt < 32768) {
            int q = pt - 28672, h4 = q >> 6, d = q & 63;
            float4 v = make_float4(mw2[d * 256 + h4 * 4 + 0], mw2[d * 256 + h4 * 4 + 1],
                                   mw2[d * 256 + h4 * 4 + 2], mw2[d * 256 + h4 * 4 + 3]);
            *(float4*)&g_mw2T4[q * 4] = v;
        } else if (pt < 33024) {
            int hh = pt - 32768;
            g_sw1last[hh] = sw1[hh * 193 + 192];
        }
        return;
    }

    __shared__ float s_h[1024];
    __shared__ float s_p[1024];
    __shared__ float s_b[1024];

    const int bn   = blockIdx.x >> 1;
    const int half = blockIdx.x & 1;
    const int c0   = half * 128;
    const int lane = tid & 31;
    const int warp = tid >> 5;
    const int pidx = blockIdx.x;

    const float4* hp4 = (const float4*)(h                + (long)bn * CDIM * DDIM + (long)c0 * DDIM);
    const float4* pp4 = (const float4*)(primitives_state + (long)bn * CDIM * DDIM + (long)c0 * DDIM);
    const float4* hb4 = (const float4*)(hebbian_traces   + (long)bn * CDIM * KDIM + (long)c0 * KDIM);

    const int v16 = tid & 15;
    const int cgr = tid >> 4;
    const int v8  = tid & 7;
    const int cb  = tid >> 3;

    // Issue ALL loads up front (20 independent LDG.128 per thread)
    float4 ha[8], pa[8], ba[4];
    #pragma unroll
    for (int j = 0; j < 8; j++) ha[j] = hp4[(cgr + 16 * j) * 16 + v16];
    #pragma unroll
    for (int j = 0; j < 8; j++) pa[j] = pp4[(cgr + 16 * j) * 16 + v16];
    #pragma unroll
    for (int j = 0; j < 4; j++) ba[j] = hb4[(cb + 32 * j) * 8 + v8];

    if (warp == 0) {
        const float* dl = decay_logit + (long)bn * CDIM + c0;
        float v = dl[lane] + dl[lane + 32] + dl[lane + 64] + dl[lane + 96];
        #pragma unroll
        for (int off = 16; off; off >>= 1) v += __shfl_down_sync(0xffffffffu, v, off);
        if (lane == 0) g_pd[pidx] = v;
    } else if (warp == 1) {
        const float* mg = msg_magnitude + (long)bn * CDIM + c0;
        float v = mg[lane] + mg[lane + 32] + mg[lane + 64] + mg[lane + 96];
        #pragma unroll
        for (int off = 16; off; off >>= 1) v += __shfl_down_sync(0xffffffffu, v, off);
        if (lane == 0) g_pmg[pidx] = v;
    }

    float4 hs, ps, bs;
    hs.x = ((ha[0].x + ha[1].x) + (ha[2].x + ha[3].x)) + ((ha[4].x + ha[5].x) + (ha[6].x + ha[7].x));
    hs.y = ((ha[0].y + ha[1].y) + (ha[2].y + ha[3].y)) + ((ha[4].y + ha[5].y) + (ha[6].y + ha[7].y));
    hs.z = ((ha[0].z + ha[1].z) + (ha[2].z + ha[3].z)) + ((ha[4].z + ha[5].z) + (ha[6].z + ha[7].z));
    hs.w = ((ha[0].w + ha[1].w) + (ha[2].w + ha[3].w)) + ((ha[4].w + ha[5].w) + (ha[6].w + ha[7].w));
    ps.x = ((pa[0].x + pa[1].x) + (pa[2].x + pa[3].x)) + ((pa[4].x + pa[5].x) + (pa[6].x + pa[7].x));
    ps.y = ((pa[0].y + pa[1].y) + (pa[2].y + pa[3].y)) + ((pa[4].y + pa[5].y) + (pa[6].y + pa[7].y));
    ps.z = ((pa[0].z + pa[1].z) + (pa[2].z + pa[3].z)) + ((pa[4].z + pa[5].z) + (pa[6].z + pa[7].z));
    ps.w = ((pa[0].w + pa[1].w) + (pa[2].w + pa[3].w)) + ((pa[4].w + pa[5].w) + (pa[6].w + pa[7].w));
    bs.x = (ba[0].x + ba[1].x) + (ba[2].x + ba[3].x);
    bs.y = (ba[0].y + ba[1].y) + (ba[2].y + ba[3].y);
    bs.z = (ba[0].z + ba[1].z) + (ba[2].z + ba[3].z);
    bs.w = (ba[0].w + ba[1].w) + (ba[2].w + ba[3].w);

    *(float4*)&s_h[cgr * 64 + v16 * 4] = hs;
    *(float4*)&s_p[cgr * 64 + v16 * 4] = ps;
    *(float4*)&s_b[cb * 32 + v8 * 4]   = bs;
    __syncthreads();

    if (tid < 64) {
        float t = 0.f;
        #pragma unroll
        for (int g = 0; g < 16; g++) t += s_h[g * 64 + tid];
        g_ph[pidx * 64 + tid] = t;
    } else if (tid < 128) {
        int d = tid - 64;
        float t = 0.f;
        #pragma unroll
        for (int g = 0; g < 16; g++) t += s_p[g * 64 + d];
        g_pp[pidx * 64 + d] = t;
    } else if (tid < 160) {
        int k = tid - 128;
        float t = 0.f;
        #pragma unroll
        for (int c2 = 0; c2 < 32; c2++) t += s_b[c2 * 32 + k];
        g_phb[pidx * 32 + k] = t;
    }
}

// ---------------- K2: mod MLP; grid 512 = (nc x 4 quarters x 2 batch-pairs); PDL on K1 ----------------
__global__ __launch_bounds__(256)
void modmlp_kernel(const float* __restrict__ mod_w1,
                   const float* __restrict__ mod_b1,
                   const float* __restrict__ mod_w2,
                   const float* __restrict__ mod_b2,
                   const float* __restrict__ neuron_id)
{
    __shared__ float s_min[2][232];
    __shared__ float s_hid[2][64];
    __shared__ float s_mm[2];
    __shared__ __align__(16) float s_nid[8][64];
    __shared__ float s_ps[4][512];
    __shared__ float s_pm[4][512];

    const int tid  = threadIdx.x;
    const int warp = tid >> 5;
    const int lane = tid & 31;
    const int nc   = blockIdx.x & 63;
    const int q    = (blockIdx.x >> 6) & 3;
    const int bp   = blockIdx.x >> 8;     // 0..1 (batch pair)
    const float inv = 1.0f / CDIM;

    // ---- PDL prologue: independent of K1 outputs ----
    if (bp == 0) {
        int c = tid >> 5, d0 = (tid & 31) * 2;
        *(float2*)&s_nid[c][d0] = *(const float2*)&neuron_id[((long)nc * CDIM + (CDIM - ALPHA) + c) * DDIM + d0];
    }

    // wait for K1 grid (partial means + repacked weights)
    cudaGridDependencySynchronize();

    // assemble mod_in for this block's 2 batches
    {
        int b2 = tid >> 7, r = tid & 127;
        int b  = bp * 2 + b2;
        int p0 = ((b * NCB + nc) << 1);
        if (r < 64) {
            s_min[b2][32 + r] = (g_ph[p0 * 64 + r] + g_ph[(p0 + 1) * 64 + r]) * inv;
        } else {
            int d = r - 64;
            s_min[b2][97 + d] = (g_pp[p0 * 64 + d] + g_pp[(p0 + 1) * 64 + d]) * inv;
        }
        if (tid < 64) {
            int bb = tid >> 5, k = tid & 31;
            int p = (((bp * 2 + bb) * NCB + nc) << 1);
            s_min[bb][k] = (g_phb[p * 32 + k] + g_phb[(p + 1) * 32 + k]) * inv;
        } else if (tid < 66) {
            int bb = tid - 64;
            int p = (((bp * 2 + bb) * NCB + nc) << 1);
            s_min[bb][96] = (g_pd[p] + g_pd[p + 1]) * inv;
        } else if (tid < 68) {
            int bb = tid - 66;
            int p = (((bp * 2 + bb) * NCB + nc) << 1);
            s_mm[bb] = (g_pmg[p] + g_pmg[p + 1]) * inv;
        }
    }
    __syncthreads();
    {
        int b2 = tid >> 7, r = tid & 127;
        if (r < 64) s_min[b2][161 + r] = s_mm[b2];
    }
    __syncthreads();

    // ---- neuron_id dots for this hh-quarter (bp==0 blocks only; c-minor output) ----
    if (bp == 0) {
        int hhl = tid & 63, ig = tid >> 6;
        int hh = q * 64 + hhl;
        float accs[8], accm[8];
        #pragma unroll
        for (int c = 0; c < 8; c++) { accs[c] = 0.f; accm[c] = 0.f; }
        #pragma unroll
        for (int s = 0; s < 4; s++) {
            int i4 = 32 + ig * 4 + s;
            int i  = (i4 - 32) * 4;
            float4 ws = *(const float4*)&g_sw1T4[(i4 * 256 + hh) * 4];
            float4 wm = *(const float4*)&g_mw1T4[(i4 * 256 + hh) * 4];
            #pragma unroll
            for (int c = 0; c < 8; c++) {
                float4 nv = *(const float4*)&s_nid[c][i];
                accs[c] += nv.x * ws.x + nv.y * ws.y + nv.z * ws.z + nv.w * ws.w;
                accm[c] += nv.x * wm.x + nv.y * wm.y + nv.z * wm.z + nv.w * wm.w;
            }
        }
        #pragma unroll
        for (int c = 0; c < 8; c++) {
            s_ps[ig][hhl * 8 + c] = accs[c];
            s_pm[ig][hhl * 8 + c] = accm[c];
        }
        __syncthreads();
        for (int o = tid; o < 512; o += 256) {
            int hhl2 = o >> 3;
            int hh2 = q * 64 + hhl2;
            int c = o & 7;
            g_ndot_s[((long)nc * 256 + hh2) * 8 + c] = s_ps[0][o] + s_ps[1][o] + s_ps[2][o] + s_ps[3][o];
            g_ndot_m[((long)nc * 256 + hh2) * 8 + c] = s_pm[0][o] + s_pm[1][o] + s_pm[2][o] + s_pm[3][o];
        }
    }

    // layer 1: 64 rows (this quarter), warp-per-row, 2 batches per weight read
    for (int r = 0; r < 8; r++) {
        int rloc = warp * 8 + r;
        int h0 = q * 64 + rloc;
        const float* row = mod_w1 + ((long)nc * HDIM + h0) * MODI;
        float a0 = 0.f, a1 = 0.f;
        #pragma unroll
        for (int j = 0; j < 7; j++) {
            int i = lane + 32 * j;
            float w = row[i];
            a0 += w * s_min[0][i];
            a1 += w * s_min[1][i];
        }
        if (lane == 0) {
            float w = row[224];
            a0 += w * s_min[0][224];
            a1 += w * s_min[1][224];
        }
        #pragma unroll
        for (int off = 16; off; off >>= 1) {
            a0 += __shfl_down_sync(0xffffffffu, a0, off);
            a1 += __shfl_down_sync(0xffffffffu, a1, off);
        }
        if (lane == 0) {
            float bias = mod_b1[nc * HDIM + h0];
            s_hid[0][rloc] = tanhf(a0 + bias);
            s_hid[1][rloc] = tanhf(a1 + bias);
        }
    }
    __syncthreads();

    // layer 2 partial over this quarter's 64 hidden units (2 batches)
    if (tid < 194) {
        int o = tid >> 1, bl = tid & 1;
        int b = bp * 2 + bl;
        const float* w2c = mod_w2 + (long)nc * HDIM * MODO + (long)(q * 64) * MODO + o;
        float a = 0.f;
        #pragma unroll 8
        for (int hh = 0; hh < 64; hh++) a += w2c[hh * MODO] * s_hid[bl][hh];
        if (q == 0) a += mod_b2[nc * MODO + o];
        g_l2p[(((long)b * NCB + nc) * 4 + q) * 100 + o] = a;
    }
}

// ---------------- K3: per-cell pipeline (packed f32x2); PDL on K2 ----------------
__global__ __launch_bounds__(512, 2)
void cellmem_kernel(
    const float* __restrict__ h,
    const float* __restrict__ prev_messages,
    const float* __restrict__ state_b1,
    const float* __restrict__ state_b2,
    const float* __restrict__ msg_b1,
    const float* __restrict__ msg_b2,
    const int*   __restrict__ conn_indices,
    float* __restrict__ out)
{
    __shared__ float s_wsig[32];
    __shared__ __align__(16) float s_prim[64];
    __shared__ float s_scal[2];
    __shared__ int   s_conn[256];
    __shared__ float s_hv[8][64];
    __shared__ __align__(16) float s_inv2f[2][8][64];
    __shared__ __align__(16) float s_invT[512];    // [d][c] — c-pairs packed
    __shared__ __align__(16) float s_hnewT[512];   // [d][c]
    __shared__ __align__(16) float s_scratch[4096];
    __shared__ __align__(16) float s_t[2048];      // [hh][c]
    __shared__ __align__(16) float s_acc8T[512];   // [d][c]

    const int tid  = threadIdx.x;
    const int warp = tid >> 5;
    const int lane = tid & 31;
    const int b    = blockIdx.x >> 6;
    const int nc   = blockIdx.x & 63;
    const long bn  = (long)b * NCB + nc;

    const float* hp = h             + bn * CDIM * DDIM;
    const float* pm = prev_messages + bn * CDIM * DDIM;

    const int d64 = tid & 63;
    const int c8  = tid >> 6;

    // ---- PDL prologue: inputs only (conn, h) — independent of K1/K2 outputs ----
    if (tid >= 256 && tid < 512) {
        int q = tid - 256;
        int cc = q >> 5, k = q & 31;
        s_conn[q] = conn_indices[((long)nc * CDIM + (CDIM - ALPHA) + cc) * KDIM + k];
    }
    s_hv[c8][d64] = hp[((CDIM - ALPHA) + c8) * DDIM + d64];

    // wait for K2 grid (l2p, ndot; K1 outputs transitively complete)
    cudaGridDependencySynchronize();

    // ---------- P1 ----------
    if (tid < MODO) {
        float v = g_l2p[(bn * 4 + 0) * 100 + tid] + g_l2p[(bn * 4 + 1) * 100 + tid]
                + g_l2p[(bn * 4 + 2) * 100 + tid] + g_l2p[(bn * 4 + 3) * 100 + tid];
        if (tid < KDIM)        s_wsig[tid] = sigm(v);
        else if (tid == KDIM) { s_scal[0] = v; s_scal[1] = sigm(v); }
        else                   s_prim[tid - KDIM - 1] = v;
    }
    __syncthreads();

    // ---------- P5: gather ----------
    {
        int cc = warp & 7, kh = warp >> 3;
        float ax = 0.f, ay = 0.f;
        #pragma unroll 4
        for (int j = 0; j < 16; j++) {
            int k = kh * 16 + j;
            const float2* p = (const float2*)(pm + (long)s_conn[cc * KDIM + k] * DDIM);
            float w = s_wsig[k];
            float2 v = p[lane];
            ax += w * v.x;
            ay += w * v.y;
        }
        s_inv2f[kh][cc][lane * 2]     = ax;
        s_inv2f[kh][cc][lane * 2 + 1] = ay;
    }
    __syncthreads();
    s_invT[d64 * 8 + c8] = s_inv2f[0][c8][d64] + s_inv2f[1][c8][d64];
    __syncthreads();

    // ---------- P6: state hidden (f32x2, direct pair loads) ----------
    {
        int hh = tid & 255, ih = tid >> 8;
        unsigned long long acc2[4];
        if (ih == 0) {
            const ulonglong2* np = (const ulonglong2*)&g_ndot_s[((long)nc * 256 + hh) * 8];
            ulonglong2 n01 = np[0], n23 = np[1];
            acc2[0] = n01.x; acc2[1] = n01.y; acc2[2] = n23.x; acc2[3] = n23.y;
        } else {
            unsigned long long z = pk(0.f, 0.f);
            acc2[0] = z; acc2[1] = z; acc2[2] = z; acc2[3] = z;
        }
        float pdot = 0.f;
        #pragma unroll
        for (int s = 0; s < 8; s++) {
            int i4 = ih * 8 + s, i = i4 * 4;
            float wa[4], wb[4];
            *(float4*)wa = *(const float4*)&g_sw1T4[(i4 * 256 + hh) * 4];
            *(float4*)wb = *(const float4*)&g_sw1T4[((i4 + 16) * 256 + hh) * 4];
            float4 pv = *(const float4*)&s_prim[i];
            pdot += pv.x * wb[0] + pv.y * wb[1] + pv.z * wb[2] + pv.w * wb[3];
            #pragma unroll
            for (int e = 0; e < 4; e++) {
                unsigned long long w2 = pk(wa[e], wa[e]);
                const ulonglong2* ivp = (const ulonglong2*)&s_invT[(i + e) * 8];
                ulonglong2 p01 = ivp[0], p23 = ivp[1];
                acc2[0] = ffma2u(w2, p01.x, acc2[0]);
                acc2[1] = ffma2u(w2, p01.y, acc2[1]);
                acc2[2] = ffma2u(w2, p23.x, acc2[2]);
                acc2[3] = ffma2u(w2, p23.y, acc2[3]);
            }
        }
        float extra = pdot;
        if (ih == 0) extra += state_b1[hh] + s_scal[0] * g_sw1last[hh];
        unsigned long long ext2 = pk(extra, extra);
        ulonglong2* op = (ulonglong2*)&s_scratch[ih * 2048 + hh * 8];
        op[0] = make_ulonglong2(add2u(acc2[0], ext2), add2u(acc2[1], ext2));
        op[1] = make_ulonglong2(add2u(acc2[2], ext2), add2u(acc2[3], ext2));
        __syncthreads();
        float4 a  = *(const float4*)&s_scratch[hh * 8 + ih * 4];
        float4 bq = *(const float4*)&s_scratch[2048 + hh * 8 + ih * 4];
        *(float4*)&s_t[hh * 8 + ih * 4] =
            make_float4(tanhf(a.x + bq.x), tanhf(a.y + bq.y), tanhf(a.z + bq.z), tanhf(a.w + bq.w));
    }
    __syncthreads();

    // ---------- P7: update + h_new (f32x2) ----------
    {
        int d = tid & 63, hq = tid >> 6;
        unsigned long long z = pk(0.f, 0.f);
        unsigned long long acc2[4] = {z, z, z, z};
        #pragma unroll
        for (int s = 0; s < 8; s++) {
            int h4 = hq * 8 + s, hh = h4 * 4;
            float wa[4];
            *(float4*)wa = *(const float4*)&g_sw2T4[(h4 * 64 + d) * 4];
            #pragma unroll
            for (int e = 0; e < 4; e++) {
                unsigned long long w2 = pk(wa[e], wa[e]);
                const ulonglong2* tp = (const ulonglong2*)&s_t[(hh + e) * 8];
                ulonglong2 p01 = tp[0], p23 = tp[1];
                acc2[0] = ffma2u(w2, p01.x, acc2[0]);
                acc2[1] = ffma2u(w2, p01.y, acc2[1]);
                acc2[2] = ffma2u(w2, p23.x, acc2[2]);
                acc2[3] = ffma2u(w2, p23.y, acc2[3]);
            }
        }
        __syncthreads();   // s_scratch free (P6 consumers done)
        ulonglong2* op = (ulonglong2*)&s_scratch[hq * 512 + d * 8];
        op[0] = make_ulonglong2(acc2[0], acc2[1]);
        op[1] = make_ulonglong2(acc2[2], acc2[3]);
        __syncthreads();
        float a = state_b2[d64];
        #pragma unroll
        for (int q = 0; q < 8; q++) a += s_scratch[q * 512 + d64 * 8 + c8];
        float ds = s_scal[1];
        s_hnewT[d64 * 8 + c8] = ds * s_hv[c8][d64] + (1.f - ds) * tanhf(a);
    }
    __syncthreads();

    // ---------- P8: msg hidden (f32x2) ----------
    {
        int hh = tid & 255, ih = tid >> 8;
        unsigned long long acc2[4];
        if (ih == 0) {
            const ulonglong2* np = (const ulonglong2*)&g_ndot_m[((long)nc * 256 + hh) * 8];
            ulonglong2 n01 = np[0], n23 = np[1];
            acc2[0] = n01.x; acc2[1] = n01.y; acc2[2] = n23.x; acc2[3] = n23.y;
        } else {
            unsigned long long z = pk(0.f, 0.f);
            acc2[0] = z; acc2[1] = z; acc2[2] = z; acc2[3] = z;
        }
        float pdot = 0.f;
        #pragma unroll
        for (int s = 0; s < 8; s++) {
            int i4 = ih * 8 + s, i = i4 * 4;
            float wa[4], wb[4];
            *(float4*)wa = *(const float4*)&g_mw1T4[(i4 * 256 + hh) * 4];
            *(float4*)wb = *(const float4*)&g_mw1T4[((i4 + 16) * 256 + hh) * 4];
            float4 pv = *(const float4*)&s_prim[i];
            pdot += pv.x * wb[0] + pv.y * wb[1] + pv.z * wb[2] + pv.w * wb[3];
            #pragma unroll
            for (int e = 0; e < 4; e++) {
                unsigned long long w2 = pk(wa[e], wa[e]);
                const ulonglong2* ivp = (const ulonglong2*)&s_hnewT[(i + e) * 8];
                ulonglong2 p01 = ivp[0], p23 = ivp[1];
                acc2[0] = ffma2u(w2, p01.x, acc2[0]);
                acc2[1] = ffma2u(w2, p01.y, acc2[1]);
                acc2[2] = ffma2u(w2, p23.x, acc2[2]);
                acc2[3] = ffma2u(w2, p23.y, acc2[3]);
            }
        }
        float extra = pdot;
        if (ih == 0) extra += msg_b1[hh];
        unsigned long long ext2 = pk(extra, extra);
        __syncthreads();   // s_scratch consumers from P7 done
        ulonglong2* op = (ulonglong2*)&s_scratch[ih * 2048 + hh * 8];
        op[0] = make_ulonglong2(add2u(acc2[0], ext2), add2u(acc2[1], ext2));
        op[1] = make_ulonglong2(add2u(acc2[2], ext2), add2u(acc2[3], ext2));
        __syncthreads();
        float4 a  = *(const float4*)&s_scratch[hh * 8 + ih * 4];
        float4 bq = *(const float4*)&s_scratch[2048 + hh * 8 + ih * 4];
        *(float4*)&s_t[hh * 8 + ih * 4] =
            make_float4(tanhf(a.x + bq.x), tanhf(a.y + bq.y), tanhf(a.z + bq.z), tanhf(a.w + bq.w));
    }
    __syncthreads();

    // ---------- P9: msg out + readout (f32x2) ----------
    {
        int d = tid & 63, hq = tid >> 6;
        unsigned long long z = pk(0.f, 0.f);
        unsigned long long acc2[4] = {z, z, z, z};
        #pragma unroll
        for (int s = 0; s < 8; s++) {
            int h4 = hq * 8 + s, hh = h4 * 4;
            float wa[4];
            *(float4*)wa = *(const float4*)&g_mw2T4[(h4 * 64 + d) * 4];
            #pragma unroll
            for (int e = 0; e < 4; e++) {
                unsigned long long w2 = pk(wa[e], wa[e]);
                const ulonglong2* tp = (const ulonglong2*)&s_t[(hh + e) * 8];
                ulonglong2 p01 = tp[0], p23 = tp[1];
                acc2[0] = ffma2u(w2, p01.x, acc2[0]);
                acc2[1] = ffma2u(w2, p01.y, acc2[1]);
                acc2[2] = ffma2u(w2, p23.x, acc2[2]);
                acc2[3] = ffma2u(w2, p23.y, acc2[3]);
            }
        }
        __syncthreads();
        ulonglong2* op = (ulonglong2*)&s_scratch[hq * 512 + d * 8];
        op[0] = make_ulonglong2(acc2[0], acc2[1]);
        op[1] = make_ulonglong2(acc2[2], acc2[3]);
        __syncthreads();
        float a = msg_b2[d64];
        #pragma unroll
        for (int q = 0; q < 8; q++) a += s_scratch[q * 512 + d64 * 8 + c8];
        s_acc8T[d64 * 8 + c8] = tanhf(a);
    }
    __syncthreads();
    if (tid < 64) {
        float4 a0 = *(const float4*)&s_acc8T[tid * 8];
        float4 a1 = *(const float4*)&s_acc8T[tid * 8 + 4];
        out[(long)b * (NCB * DDIM) + nc * DDIM + tid] =
            ((a0.x + a0.y) + (a0.z + a0.w) + (a1.x + a1.y) + (a1.z + a1.w)) * 0.125f;
    }
}

extern "C" void kernel_launch(void* const* d_in, const int* in_sizes, int n_in,
                              void* d_out, int out_size)
{
    const float* h          = (const float*)d_in[0];
    const float* prev_msg   = (const float*)d_in[1];
    const float* decay      = (const float*)d_in[2];
    const float* prim       = (const float*)d_in[3];
    const float* hebb       = (const float*)d_in[4];
    const float* msgmag     = (const float*)d_in[5];
    // d_in[6] = cc_signals : dead (injection hits cells < ALPHA; output reads cells >= C-ALPHA)
    const float* state_w1   = (const float*)d_in[7];
    const float* state_b1   = (const float*)d_in[8];
    const float* state_w2   = (const float*)d_in[9];
    const float* state_b2   = (const float*)d_in[10];
    const float* msg_w1     = (const float*)d_in[11];
    const float* msg_b1     = (const float*)d_in[12];
    const float* msg_w2     = (const float*)d_in[13];
    const float* msg_b2     = (const float*)d_in[14];
    const float* mod_w1     = (const float*)d_in[15];
    const float* mod_b1     = (const float*)d_in[16];
    const float* mod_w2     = (const float*)d_in[17];
    const float* mod_b2     = (const float*)d_in[18];
    const float* neuron_id  = (const float*)d_in[19];
    const int*   conn       = (const int*)d_in[20];
    float* outp             = (float*)d_out;

    // K1: normal launch
    means_prep_kernel<<<MEANS_BLOCKS + PREP_BLOCKS, 256>>>(
        h, prim, hebb, decay, msgmag, state_w1, msg_w1, state_w2, msg_w2);

    // K2: PDL — overlap prologue with K1 tail
    {
        cudaLaunchConfig_t cfg = {};
        cfg.gridDim  = dim3(512, 1, 1);
        cfg.blockDim = dim3(256, 1, 1);
        cudaLaunchAttribute attrs[1];
        attrs[0].id = cudaLaunchAttributeProgrammaticStreamSerialization;
        attrs[0].val.programmaticStreamSerializationAllowed = 1;
        cfg.attrs = attrs;
        cfg.numAttrs = 1;
        cudaLaunchKernelEx(&cfg, modmlp_kernel, mod_w1, mod_b1, mod_w2, mod_b2, neuron_id);
    }

    // K3: PDL — overlap prologue (conn/h loads) with K2 tail
    {
        cudaLaunchConfig_t cfg = {};
        cfg.gridDim  = dim3(256, 1, 1);
        cfg.blockDim = dim3(512, 1, 1);
        cudaLaunchAttribute attrs[1];
        attrs[0].id = cudaLaunchAttributeProgrammaticStreamSerialization;
        attrs[0].val.programmaticStreamSerializationAllowed = 1;
        cfg.attrs = attrs;
        cfg.numAttrs = 1;
        cudaLaunchKernelEx(&cfg, cellmem_kernel, h, prev_msg,
                           state_b1, state_b2, msg_b1, msg_b2, conn, outp);
    }
}

// round 13
// speedup vs baseline: 1.1250x; 1.0399x over previous
#include <cuda_runtime.h>
#include <math.h>

#define NCB   64
#define CDIM  256
#define DDIM  64
#define KDIM  32
#define ALPHA 8
#define HDIM  256
#define MODI  225   // K + 3D + 1
#define MODO  97    // K + 1 + D

// Fast transcendentals via MUFU.EX2 / MUFU.RCP (rel err ~1e-6, budget 1e-3)
__device__ __forceinline__ float sigm(float x) {
    return __fdividef(1.0f, 1.0f + __expf(-x));
}
__device__ __forceinline__ float ftanh(float x) {
    return 1.0f - __fdividef(2.0f, __expf(2.0f * x) + 1.0f);
}

// packed f32x2 helpers (Blackwell fma.rn.f32x2 / add.rn.f32x2 — not emitted by ptxas from C++)
__device__ __forceinline__ unsigned long long pk(float x, float y) {
    unsigned long long u;
    asm("mov.b64 %0, {%1, %2};" : "=l"(u) : "f"(x), "f"(y));
    return u;
}
__device__ __forceinline__ unsigned long long ffma2u(unsigned long long a, unsigned long long b, unsigned long long c) {
    unsigned long long d;
    asm("fma.rn.f32x2 %0, %1, %2, %3;" : "=l"(d) : "l"(a), "l"(b), "l"(c));
    return d;
}
__device__ __forceinline__ unsigned long long add2u(unsigned long long a, unsigned long long b) {
    unsigned long long d;
    asm("add.rn.f32x2 %0, %1, %2;" : "=l"(d) : "l"(a), "l"(b));
    return d;
}

// float4-interleaved transposed weights:  g_sw1T4[((i/4)*256 + h)*4 + (i%4)] = sw1[h][i]
__device__ float g_sw1T4[48 * 256 * 4];
__device__ float g_mw1T4[48 * 256 * 4];
__device__ float g_sw1last[256];          // sw1[h][192]
__device__ float g_sw2T4[64 * 64 * 4];    // [((h/4)*64 + d)*4 + h%4] = sw2[d][h]
__device__ float g_mw2T4[64 * 64 * 4];

// Partial means scratch: 512 half-bn blocks
__device__ float g_ph [512 * 64];
__device__ float g_pp [512 * 64];
__device__ float g_phb[512 * 32];
__device__ float g_pd [512];
__device__ float g_pmg[512];

// mod MLP layer-2 partials: [bn][q][100] (bias folded into q=0; raw, pre-sigmoid)
__device__ float g_l2p[256 * 4 * 100];

// per-nc neuron_id dot products: [nc][hh][c]  (c-minor; shared across the 4 batches)
__device__ float g_ndot_s[64 * 256 * 8];
__device__ float g_ndot_m[64 * 256 * 8];

#define MEANS_BLOCKS 512
#define PREP_BLOCKS  129

// ---------------- K1: partial means (blocks 0..511) + weight repack (512..640) ----------------
__global__ __launch_bounds__(256)
void means_prep_kernel(const float* __restrict__ h,
                       const float* __restrict__ primitives_state,
                       const float* __restrict__ hebbian_traces,
                       const float* __restrict__ decay_logit,
                       const float* __restrict__ msg_magnitude,
                       const float* __restrict__ sw1,
                       const float* __restrict__ mw1,
                       const float* __restrict__ sw2,
                       const float* __restrict__ mw2)
{
    const int tid = threadIdx.x;

    if (blockIdx.x >= MEANS_BLOCKS) {
        int pt = (blockIdx.x - MEANS_BLOCKS) * 256 + tid;
        if (pt < 12288) {
            int i4 = pt >> 8, hh = pt & 255;
            float4 v = make_float4(sw1[hh * 193 + i4 * 4 + 0], sw1[hh * 193 + i4 * 4 + 1],
                                   sw1[hh * 193 + i4 * 4 + 2], sw1[hh * 193 + i4 * 4 + 3]);
            *(float4*)&g_sw1T4[pt * 4] = v;
        } else if (pt < 24576) {
            int q = pt - 12288, i4 = q >> 8, hh = q & 255;
            float4 v = make_float4(mw1[hh * 192 + i4 * 4 + 0], mw1[hh * 192 + i4 * 4 + 1],
                                   mw1[hh * 192 + i4 * 4 + 2], mw1[hh * 192 + i4 * 4 + 3]);
            *(float4*)&g_mw1T4[q * 4] = v;
        } else if (pt < 28672) {
            int q = pt - 24576, h4 = q >> 6, d = q & 63;
            float4 v = make_float4(sw2[d * 256 + h4 * 4 + 0], sw2[d * 256 + h4 * 4 + 1],
                                   sw2[d * 256 + h4 * 4 + 2], sw2[d * 256 + h4 * 4 + 3]);
            *(float4*)&g_sw2T4[q * 4] = v;
        } else if (pt < 32768) {
            int q = pt - 28672, h4 = q >> 6, d = q & 63;
            float4 v = make_float4(mw2[d * 256 + h4 * 4 + 0], mw2[d * 256 + h4 * 4 + 1],
                                   mw2[d * 256 + h4 * 4 + 2], mw2[d * 256 + h4 * 4 + 3]);
            *(float4*)&g_mw2T4[q * 4] = v;
        } else if (pt < 33024) {
            int hh = pt - 32768;
            g_sw1last[hh] = sw1[hh * 193 + 192];
        }
        return;
    }

    __shared__ float s_h[1024];
    __shared__ float s_p[1024];
    __shared__ float s_b[1024];

    const int bn   = blockIdx.x >> 1;
    const int half = blockIdx.x & 1;
    const int c0   = half * 128;
    const int lane = tid & 31;
    const int warp = tid >> 5;
    const int pidx = blockIdx.x;

    const float4* hp4 = (const float4*)(h                + (long)bn * CDIM * DDIM + (long)c0 * DDIM);
    const float4* pp4 = (const float4*)(primitives_state + (long)bn * CDIM * DDIM + (long)c0 * DDIM);
    const float4* hb4 = (const float4*)(hebbian_traces   + (long)bn * CDIM * KDIM + (long)c0 * KDIM);

    const int v16 = tid & 15;
    const int cgr = tid >> 4;
    const int v8  = tid & 7;
    const int cb  = tid >> 3;

    // Issue ALL loads up front (20 independent LDG.128 per thread)
    float4 ha[8], pa[8], ba[4];
    #pragma unroll
    for (int j = 0; j < 8; j++) ha[j] = hp4[(cgr + 16 * j) * 16 + v16];
    #pragma unroll
    for (int j = 0; j < 8; j++) pa[j] = pp4[(cgr + 16 * j) * 16 + v16];
    #pragma unroll
    for (int j = 0; j < 4; j++) ba[j] = hb4[(cb + 32 * j) * 8 + v8];

    if (warp == 0) {
        const float* dl = decay_logit + (long)bn * CDIM + c0;
        float v = dl[lane] + dl[lane + 32] + dl[lane + 64] + dl[lane + 96];
        #pragma unroll
        for (int off = 16; off; off >>= 1) v += __shfl_down_sync(0xffffffffu, v, off);
        if (lane == 0) g_pd[pidx] = v;
    } else if (warp == 1) {
        const float* mg = msg_magnitude + (long)bn * CDIM + c0;
        float v = mg[lane] + mg[lane + 32] + mg[lane + 64] + mg[lane + 96];
        #pragma unroll
        for (int off = 16; off; off >>= 1) v += __shfl_down_sync(0xffffffffu, v, off);
        if (lane == 0) g_pmg[pidx] = v;
    }

    float4 hs, ps, bs;
    hs.x = ((ha[0].x + ha[1].x) + (ha[2].x + ha[3].x)) + ((ha[4].x + ha[5].x) + (ha[6].x + ha[7].x));
    hs.y = ((ha[0].y + ha[1].y) + (ha[2].y + ha[3].y)) + ((ha[4].y + ha[5].y) + (ha[6].y + ha[7].y));
    hs.z = ((ha[0].z + ha[1].z) + (ha[2].z + ha[3].z)) + ((ha[4].z + ha[5].z) + (ha[6].z + ha[7].z));
    hs.w = ((ha[0].w + ha[1].w) + (ha[2].w + ha[3].w)) + ((ha[4].w + ha[5].w) + (ha[6].w + ha[7].w));
    ps.x = ((pa[0].x + pa[1].x) + (pa[2].x + pa[3].x)) + ((pa[4].x + pa[5].x) + (pa[6].x + pa[7].x));
    ps.y = ((pa[0].y + pa[1].y) + (pa[2].y + pa[3].y)) + ((pa[4].y + pa[5].y) + (pa[6].y + pa[7].y));
    ps.z = ((pa[0].z + pa[1].z) + (pa[2].z + pa[3].z)) + ((pa[4].z + pa[5].z) + (pa[6].z + pa[7].z));
    ps.w = ((pa[0].w + pa[1].w) + (pa[2].w + pa[3].w)) + ((pa[4].w + pa[5].w) + (pa[6].w + pa[7].w));
    bs.x = (ba[0].x + ba[1].x) + (ba[2].x + ba[3].x);
    bs.y = (ba[0].y + ba[1].y) + (ba[2].y + ba[3].y);
    bs.z = (ba[0].z + ba[1].z) + (ba[2].z + ba[3].z);
    bs.w = (ba[0].w + ba[1].w) + (ba[2].w + ba[3].w);

    *(float4*)&s_h[cgr * 64 + v16 * 4] = hs;
    *(float4*)&s_p[cgr * 64 + v16 * 4] = ps;
    *(float4*)&s_b[cb * 32 + v8 * 4]   = bs;
    __syncthreads();

    if (tid < 64) {
        float t = 0.f;
        #pragma unroll
        for (int g = 0; g < 16; g++) t += s_h[g * 64 + tid];
        g_ph[pidx * 64 + tid] = t;
    } else if (tid < 128) {
        int d = tid - 64;
        float t = 0.f;
        #pragma unroll
        for (int g = 0; g < 16; g++) t += s_p[g * 64 + d];
        g_pp[pidx * 64 + d] = t;
    } else if (tid < 160) {
        int k = tid - 128;
        float t = 0.f;
        #pragma unroll
        for (int c2 = 0; c2 < 32; c2++) t += s_b[c2 * 32 + k];
        g_phb[pidx * 32 + k] = t;
    }
}

// ---------------- K2: mod MLP; grid 512 = (nc x 4 quarters x 2 batch-pairs); PDL on K1 ----------------
__global__ __launch_bounds__(256)
void modmlp_kernel(const float* __restrict__ mod_w1,
                   const float* __restrict__ mod_b1,
                   const float* __restrict__ mod_w2,
                   const float* __restrict__ mod_b2,
                   const float* __restrict__ neuron_id)
{
    __shared__ float s_min[2][232];
    __shared__ float s_hid[2][64];
    __shared__ float s_mm[2];
    __shared__ __align__(16) float s_nid[8][64];
    __shared__ float s_ps[4][512];
    __shared__ float s_pm[4][512];

    const int tid  = threadIdx.x;
    const int warp = tid >> 5;
    const int lane = tid & 31;
    const int nc   = blockIdx.x & 63;
    const int q    = (blockIdx.x >> 6) & 3;
    const int bp   = blockIdx.x >> 8;     // 0..1 (batch pair)
    const float inv = 1.0f / CDIM;

    // ---- PDL prologue: independent of K1 outputs ----
    if (bp == 0) {
        int c = tid >> 5, d0 = (tid & 31) * 2;
        *(float2*)&s_nid[c][d0] = *(const float2*)&neuron_id[((long)nc * CDIM + (CDIM - ALPHA) + c) * DDIM + d0];
    }

    cudaGridDependencySynchronize();

    // assemble mod_in for this block's 2 batches
    {
        int b2 = tid >> 7, r = tid & 127;
        int b  = bp * 2 + b2;
        int p0 = ((b * NCB + nc) << 1);
        if (r < 64) {
            s_min[b2][32 + r] = (g_ph[p0 * 64 + r] + g_ph[(p0 + 1) * 64 + r]) * inv;
        } else {
            int d = r - 64;
            s_min[b2][97 + d] = (g_pp[p0 * 64 + d] + g_pp[(p0 + 1) * 64 + d]) * inv;
        }
        if (tid < 64) {
            int bb = tid >> 5, k = tid & 31;
            int p = (((bp * 2 + bb) * NCB + nc) << 1);
            s_min[bb][k] = (g_phb[p * 32 + k] + g_phb[(p + 1) * 32 + k]) * inv;
        } else if (tid < 66) {
            int bb = tid - 64;
            int p = (((bp * 2 + bb) * NCB + nc) << 1);
            s_min[bb][96] = (g_pd[p] + g_pd[p + 1]) * inv;
        } else if (tid < 68) {
            int bb = tid - 66;
            int p = (((bp * 2 + bb) * NCB + nc) << 1);
            s_mm[bb] = (g_pmg[p] + g_pmg[p + 1]) * inv;
        }
    }
    __syncthreads();
    {
        int b2 = tid >> 7, r = tid & 127;
        if (r < 64) s_min[b2][161 + r] = s_mm[b2];
    }
    __syncthreads();

    // ---- neuron_id dots for this hh-quarter (bp==0 blocks only; c-minor output) ----
    if (bp == 0) {
        int hhl = tid & 63, ig = tid >> 6;
        int hh = q * 64 + hhl;
        float accs[8], accm[8];
        #pragma unroll
        for (int c = 0; c < 8; c++) { accs[c] = 0.f; accm[c] = 0.f; }
        #pragma unroll
        for (int s = 0; s < 4; s++) {
            int i4 = 32 + ig * 4 + s;
            int i  = (i4 - 32) * 4;
            float4 ws = *(const float4*)&g_sw1T4[(i4 * 256 + hh) * 4];
            float4 wm = *(const float4*)&g_mw1T4[(i4 * 256 + hh) * 4];
            #pragma unroll
            for (int c = 0; c < 8; c++) {
                float4 nv = *(const float4*)&s_nid[c][i];
                accs[c] += nv.x * ws.x + nv.y * ws.y + nv.z * ws.z + nv.w * ws.w;
                accm[c] += nv.x * wm.x + nv.y * wm.y + nv.z * wm.z + nv.w * wm.w;
            }
        }
        #pragma unroll
        for (int c = 0; c < 8; c++) {
            s_ps[ig][hhl * 8 + c] = accs[c];
            s_pm[ig][hhl * 8 + c] = accm[c];
        }
        __syncthreads();
        for (int o = tid; o < 512; o += 256) {
            int hhl2 = o >> 3;
            int hh2 = q * 64 + hhl2;
            int c = o & 7;
            g_ndot_s[((long)nc * 256 + hh2) * 8 + c] = s_ps[0][o] + s_ps[1][o] + s_ps[2][o] + s_ps[3][o];
            g_ndot_m[((long)nc * 256 + hh2) * 8 + c] = s_pm[0][o] + s_pm[1][o] + s_pm[2][o] + s_pm[3][o];
        }
    }

    // layer 1: 64 rows (this quarter), warp-per-row, 2 batches per weight read
    for (int r = 0; r < 8; r++) {
        int rloc = warp * 8 + r;
        int h0 = q * 64 + rloc;
        const float* row = mod_w1 + ((long)nc * HDIM + h0) * MODI;
        float a0 = 0.f, a1 = 0.f;
        #pragma unroll
        for (int j = 0; j < 7; j++) {
            int i = lane + 32 * j;
            float w = row[i];
            a0 += w * s_min[0][i];
            a1 += w * s_min[1][i];
        }
        if (lane == 0) {
            float w = row[224];
            a0 += w * s_min[0][224];
            a1 += w * s_min[1][224];
        }
        #pragma unroll
        for (int off = 16; off; off >>= 1) {
            a0 += __shfl_down_sync(0xffffffffu, a0, off);
            a1 += __shfl_down_sync(0xffffffffu, a1, off);
        }
        if (lane == 0) {
            float bias = mod_b1[nc * HDIM + h0];
            s_hid[0][rloc] = ftanh(a0 + bias);
            s_hid[1][rloc] = ftanh(a1 + bias);
        }
    }
    __syncthreads();

    // layer 2 partial over this quarter's 64 hidden units (2 batches)
    if (tid < 194) {
        int o = tid >> 1, bl = tid & 1;
        int b = bp * 2 + bl;
        const float* w2c = mod_w2 + (long)nc * HDIM * MODO + (long)(q * 64) * MODO + o;
        float a = 0.f;
        #pragma unroll 8
        for (int hh = 0; hh < 64; hh++) a += w2c[hh * MODO] * s_hid[bl][hh];
        if (q == 0) a += mod_b2[nc * MODO + o];
        g_l2p[(((long)b * NCB + nc) * 4 + q) * 100 + o] = a;
    }
}

// ---------------- K3: per-cell pipeline (packed f32x2); PDL on K2 ----------------
__global__ __launch_bounds__(512, 2)
void cellmem_kernel(
    const float* __restrict__ h,
    const float* __restrict__ prev_messages,
    const float* __restrict__ state_b1,
    const float* __restrict__ state_b2,
    const float* __restrict__ msg_b1,
    const float* __restrict__ msg_b2,
    const int*   __restrict__ conn_indices,
    float* __restrict__ out)
{
    __shared__ float s_wsig[32];
    __shared__ __align__(16) float s_prim[64];
    __shared__ float s_scal[2];
    __shared__ int   s_conn[256];
    __shared__ float s_hv[8][64];
    __shared__ __align__(16) float s_inv2f[2][8][64];
    __shared__ __align__(16) float s_invT[512];    // [d][c] — c-pairs packed
    __shared__ __align__(16) float s_hnewT[512];   // [d][c]
    __shared__ __align__(16) float s_scratch[4096];
    __shared__ __align__(16) float s_t[2048];      // [hh][c]
    __shared__ __align__(16) float s_acc8T[512];   // [d][c]

    const int tid  = threadIdx.x;
    const int warp = tid >> 5;
    const int lane = tid & 31;
    const int b    = blockIdx.x >> 6;
    const int nc   = blockIdx.x & 63;
    const long bn  = (long)b * NCB + nc;

    const float* hp = h             + bn * CDIM * DDIM;
    const float* pm = prev_messages + bn * CDIM * DDIM;

    const int d64 = tid & 63;
    const int c8  = tid >> 6;

    // ---- PDL prologue: inputs only (conn, h) — independent of K1/K2 outputs ----
    if (tid >= 256 && tid < 512) {
        int q = tid - 256;
        int cc = q >> 5, k = q & 31;
        s_conn[q] = conn_indices[((long)nc * CDIM + (CDIM - ALPHA) + cc) * KDIM + k];
    }
    s_hv[c8][d64] = hp[((CDIM - ALPHA) + c8) * DDIM + d64];

    cudaGridDependencySynchronize();

    // ---------- P1 ----------
    if (tid < MODO) {
        float v = g_l2p[(bn * 4 + 0) * 100 + tid] + g_l2p[(bn * 4 + 1) * 100 + tid]
                + g_l2p[(bn * 4 + 2) * 100 + tid] + g_l2p[(bn * 4 + 3) * 100 + tid];
        if (tid < KDIM)        s_wsig[tid] = sigm(v);
        else if (tid == KDIM) { s_scal[0] = v; s_scal[1] = sigm(v); }
        else                   s_prim[tid - KDIM - 1] = v;
    }
    __syncthreads();

    // ---------- P5: gather ----------
    {
        int cc = warp & 7, kh = warp >> 3;
        float ax = 0.f, ay = 0.f;
        #pragma unroll 4
        for (int j = 0; j < 16; j++) {
            int k = kh * 16 + j;
            const float2* p = (const float2*)(pm + (long)s_conn[cc * KDIM + k] * DDIM);
            float w = s_wsig[k];
            float2 v = p[lane];
            ax += w * v.x;
            ay += w * v.y;
        }
        s_inv2f[kh][cc][lane * 2]     = ax;
        s_inv2f[kh][cc][lane * 2 + 1] = ay;
    }
    __syncthreads();
    s_invT[d64 * 8 + c8] = s_inv2f[0][c8][d64] + s_inv2f[1][c8][d64];
    __syncthreads();

    // ---------- P6: state hidden (f32x2, direct pair loads) ----------
    {
        int hh = tid & 255, ih = tid >> 8;
        unsigned long long acc2[4];
        if (ih == 0) {
            const ulonglong2* np = (const ulonglong2*)&g_ndot_s[((long)nc * 256 + hh) * 8];
            ulonglong2 n01 = np[0], n23 = np[1];
            acc2[0] = n01.x; acc2[1] = n01.y; acc2[2] = n23.x; acc2[3] = n23.y;
        } else {
            unsigned long long z = pk(0.f, 0.f);
            acc2[0] = z; acc2[1] = z; acc2[2] = z; acc2[3] = z;
        }
        float pdot = 0.f;
        #pragma unroll
        for (int s = 0; s < 8; s++) {
            int i4 = ih * 8 + s, i = i4 * 4;
            float wa[4], wb[4];
            *(float4*)wa = *(const float4*)&g_sw1T4[(i4 * 256 + hh) * 4];
            *(float4*)wb = *(const float4*)&g_sw1T4[((i4 + 16) * 256 + hh) * 4];
            float4 pv = *(const float4*)&s_prim[i];
            pdot += pv.x * wb[0] + pv.y * wb[1] + pv.z * wb[2] + pv.w * wb[3];
            #pragma unroll
            for (int e = 0; e < 4; e++) {
                unsigned long long w2 = pk(wa[e], wa[e]);
                const ulonglong2* ivp = (const ulonglong2*)&s_invT[(i + e) * 8];
                ulonglong2 p01 = ivp[0], p23 = ivp[1];
                acc2[0] = ffma2u(w2, p01.x, acc2[0]);
                acc2[1] = ffma2u(w2, p01.y, acc2[1]);
                acc2[2] = ffma2u(w2, p23.x, acc2[2]);
                acc2[3] = ffma2u(w2, p23.y, acc2[3]);
            }
        }
        float extra = pdot;
        if (ih == 0) extra += state_b1[hh] + s_scal[0] * g_sw1last[hh];
        unsigned long long ext2 = pk(extra, extra);
        ulonglong2* op = (ulonglong2*)&s_scratch[ih * 2048 + hh * 8];
        op[0] = make_ulonglong2(add2u(acc2[0], ext2), add2u(acc2[1], ext2));
        op[1] = make_ulonglong2(add2u(acc2[2], ext2), add2u(acc2[3], ext2));
        __syncthreads();
        float4 a  = *(const float4*)&s_scratch[hh * 8 + ih * 4];
        float4 bq = *(const float4*)&s_scratch[2048 + hh * 8 + ih * 4];
        *(float4*)&s_t[hh * 8 + ih * 4] =
            make_float4(ftanh(a.x + bq.x), ftanh(a.y + bq.y), ftanh(a.z + bq.z), ftanh(a.w + bq.w));
    }
    __syncthreads();

    // ---------- P7: update + h_new (f32x2) ----------
    {
        int d = tid & 63, hq = tid >> 6;
        unsigned long long z = pk(0.f, 0.f);
        unsigned long long acc2[4] = {z, z, z, z};
        #pragma unroll
        for (int s = 0; s < 8; s++) {
            int h4 = hq * 8 + s, hh = h4 * 4;
            float wa[4];
            *(float4*)wa = *(const float4*)&g_sw2T4[(h4 * 64 + d) * 4];
            #pragma unroll
            for (int e = 0; e < 4; e++) {
                unsigned long long w2 = pk(wa[e], wa[e]);
                const ulonglong2* tp = (const ulonglong2*)&s_t[(hh + e) * 8];
                ulonglong2 p01 = tp[0], p23 = tp[1];
                acc2[0] = ffma2u(w2, p01.x, acc2[0]);
                acc2[1] = ffma2u(w2, p01.y, acc2[1]);
                acc2[2] = ffma2u(w2, p23.x, acc2[2]);
                acc2[3] = ffma2u(w2, p23.y, acc2[3]);
            }
        }
        __syncthreads();   // s_scratch free (P6 consumers done)
        ulonglong2* op = (ulonglong2*)&s_scratch[hq * 512 + d * 8];
        op[0] = make_ulonglong2(acc2[0], acc2[1]);
        op[1] = make_ulonglong2(acc2[2], acc2[3]);
        __syncthreads();
        float a = state_b2[d64];
        #pragma unroll
        for (int q = 0; q < 8; q++) a += s_scratch[q * 512 + d64 * 8 + c8];
        float ds = s_scal[1];
        s_hnewT[d64 * 8 + c8] = ds * s_hv[c8][d64] + (1.f - ds) * ftanh(a);
    }
    __syncthreads();

    // ---------- P8: msg hidden (f32x2) ----------
    {
        int hh = tid & 255, ih = tid >> 8;
        unsigned long long acc2[4];
        if (ih == 0) {
            const ulonglong2* np = (const ulonglong2*)&g_ndot_m[((long)nc * 256 + hh) * 8];
            ulonglong2 n01 = np[0], n23 = np[1];
            acc2[0] = n01.x; acc2[1] = n01.y; acc2[2] = n23.x; acc2[3] = n23.y;
        } else {
            unsigned long long z = pk(0.f, 0.f);
            acc2[0] = z; acc2[1] = z; acc2[2] = z; acc2[3] = z;
        }
        float pdot = 0.f;
        #pragma unroll
        for (int s = 0; s < 8; s++) {
            int i4 = ih * 8 + s, i = i4 * 4;
            float wa[4], wb[4];
            *(float4*)wa = *(const float4*)&g_mw1T4[(i4 * 256 + hh) * 4];
            *(float4*)wb = *(const float4*)&g_mw1T4[((i4 + 16) * 256 + hh) * 4];
            float4 pv = *(const float4*)&s_prim[i];
            pdot += pv.x * wb[0] + pv.y * wb[1] + pv.z * wb[2] + pv.w * wb[3];
            #pragma unroll
            for (int e = 0; e < 4; e++) {
                unsigned long long w2 = pk(wa[e], wa[e]);
                const ulonglong2* ivp = (const ulonglong2*)&s_hnewT[(i + e) * 8];
                ulonglong2 p01 = ivp[0], p23 = ivp[1];
                acc2[0] = ffma2u(w2, p01.x, acc2[0]);
                acc2[1] = ffma2u(w2, p01.y, acc2[1]);
                acc2[2] = ffma2u(w2, p23.x, acc2[2]);
                acc2[3] = ffma2u(w2, p23.y, acc2[3]);
            }
        }
        float extra = pdot;
        if (ih == 0) extra += msg_b1[hh];
        unsigned long long ext2 = pk(extra, extra);
        __syncthreads();   // s_scratch consumers from P7 done
        ulonglong2* op = (ulonglong2*)&s_scratch[ih * 2048 + hh * 8];
        op[0] = make_ulonglong2(add2u(acc2[0], ext2), add2u(acc2[1], ext2));
        op[1] = make_ulonglong2(add2u(acc2[2], ext2), add2u(acc2[3], ext2));
        __syncthreads();
        float4 a  = *(const float4*)&s_scratch[hh * 8 + ih * 4];
        float4 bq = *(const float4*)&s_scratch[2048 + hh * 8 + ih * 4];
        *(float4*)&s_t[hh * 8 + ih * 4] =
            make_float4(ftanh(a.x + bq.x), ftanh(a.y + bq.y), ftanh(a.z + bq.z), ftanh(a.w + bq.w));
    }
    __syncthreads();

    // ---------- P9: msg out + readout (f32x2) ----------
    {
        int d = tid & 63, hq = tid >> 6;
        unsigned long long z = pk(0.f, 0.f);
        unsigned long long acc2[4] = {z, z, z, z};
        #pragma unroll
        for (int s = 0; s < 8; s++) {
            int h4 = hq * 8 + s, hh = h4 * 4;
            float wa[4];
            *(float4*)wa = *(const float4*)&g_mw2T4[(h4 * 64 + d) * 4];
            #pragma unroll
            for (int e = 0; e < 4; e++) {
                unsigned long long w2 = pk(wa[e], wa[e]);
                const ulonglong2* tp = (const ulonglong2*)&s_t[(hh + e) * 8];
                ulonglong2 p01 = tp[0], p23 = tp[1];
                acc2[0] = ffma2u(w2, p01.x, acc2[0]);
                acc2[1] = ffma2u(w2, p01.y, acc2[1]);
                acc2[2] = ffma2u(w2, p23.x, acc2[2]);
                acc2[3] = ffma2u(w2, p23.y, acc2[3]);
            }
        }
        __syncthreads();
        ulonglong2* op = (ulonglong2*)&s_scratch[hq * 512 + d * 8];
        op[0] = make_ulonglong2(acc2[0], acc2[1]);
        op[1] = make_ulonglong2(acc2[2], acc2[3]);
        __syncthreads();
        float a = msg_b2[d64];
        #pragma unroll
        for (int q = 0; q < 8; q++) a += s_scratch[q * 512 + d64 * 8 + c8];
        s_acc8T[d64 * 8 + c8] = ftanh(a);
    }
    __syncthreads();
    if (tid < 64) {
        float4 a0 = *(const float4*)&s_acc8T[tid * 8];
        float4 a1 = *(const float4*)&s_acc8T[tid * 8 + 4];
        out[(long)b * (NCB * DDIM) + nc * DDIM + tid] =
            ((a0.x + a0.y) + (a0.z + a0.w) + (a1.x + a1.y) + (a1.z + a1.w)) * 0.125f;
    }
}

extern "C" void kernel_launch(void* const* d_in, const int* in_sizes, int n_in,
                              void* d_out, int out_size)
{
    const float* h          = (const float*)d_in[0];
    const float* prev_msg   = (const float*)d_in[1];
    const float* decay      = (const float*)d_in[2];
    const float* prim       = (const float*)d_in[3];
    const float* hebb       = (const float*)d_in[4];
    const float* msgmag     = (const float*)d_in[5];
    // d_in[6] = cc_signals : dead (injection hits cells < ALPHA; output reads cells >= C-ALPHA)
    const float* state_w1   = (const float*)d_in[7];
    const float* state_b1   = (const float*)d_in[8];
    const float* state_w2   = (const float*)d_in[9];
    const float* state_b2   = (const float*)d_in[10];
    const float* msg_w1     = (const float*)d_in[11];
    const float* msg_b1     = (const float*)d_in[12];
    const float* msg_w2     = (const float*)d_in[13];
    const float* msg_b2     = (const float*)d_in[14];
    const float* mod_w1     = (const float*)d_in[15];
    const float* mod_b1     = (const float*)d_in[16];
    const float* mod_w2     = (const float*)d_in[17];
    const float* mod_b2     = (const float*)d_in[18];
    const float* neuron_id  = (const float*)d_in[19];
    const int*   conn       = (const int*)d_in[20];
    float* outp             = (float*)d_out;

    // K1: normal launch
    means_prep_kernel<<<MEANS_BLOCKS + PREP_BLOCKS, 256>>>(
        h, prim, hebb, decay, msgmag, state_w1, msg_w1, state_w2, msg_w2);

    // K2: PDL — overlap prologue with K1 tail
    {
        cudaLaunchConfig_t cfg = {};
        cfg.gridDim  = dim3(512, 1, 1);
        cfg.blockDim = dim3(256, 1, 1);
        cudaLaunchAttribute attrs[1];
        attrs[0].id = cudaLaunchAttributeProgrammaticStreamSerialization;
        attrs[0].val.programmaticStreamSerializationAllowed = 1;
        cfg.attrs = attrs;
        cfg.numAttrs = 1;
        cudaLaunchKernelEx(&cfg, modmlp_kernel, mod_w1, mod_b1, mod_w2, mod_b2, neuron_id);
    }

    // K3: PDL — overlap prologue (conn/h loads) with K2 tail
    {
        cudaLaunchConfig_t cfg = {};
        cfg.gridDim  = dim3(256, 1, 1);
        cfg.blockDim = dim3(512, 1, 1);
        cudaLaunchAttribute attrs[1];
        attrs[0].id = cudaLaunchAttributeProgrammaticStreamSerialization;
        attrs[0].val.programmaticStreamSerializationAllowed = 1;
        cfg.attrs = attrs;
        cfg.numAttrs = 1;
        cudaLaunchKernelEx(&cfg, cellmem_kernel, h, prev_msg,
                           state_b1, state_b2, msg_b1, msg_b2, conn, outp);
    }
}

// round 14
// speedup vs baseline: 1.1917x; 1.0593x over previous
#include <cuda_runtime.h>
#include <math.h>

#define NCB   64
#define CDIM  256
#define DDIM  64
#define KDIM  32
#define ALPHA 8
#define HDIM  256
#define MODI  225   // K + 3D + 1
#define MODO  97    // K + 1 + D

// Fast transcendentals via MUFU.EX2 / MUFU.RCP (rel err ~1e-6, budget 1e-3)
__device__ __forceinline__ float sigm(float x) {
    return __fdividef(1.0f, 1.0f + __expf(-x));
}
__device__ __forceinline__ float ftanh(float x) {
    return 1.0f - __fdividef(2.0f, __expf(2.0f * x) + 1.0f);
}

// packed f32x2 helpers (Blackwell fma.rn.f32x2 / add.rn.f32x2 — not emitted by ptxas from C++)
__device__ __forceinline__ unsigned long long pk(float x, float y) {
    unsigned long long u;
    asm("mov.b64 %0, {%1, %2};" : "=l"(u) : "f"(x), "f"(y));
    return u;
}
__device__ __forceinline__ unsigned long long ffma2u(unsigned long long a, unsigned long long b, unsigned long long c) {
    unsigned long long d;
    asm("fma.rn.f32x2 %0, %1, %2, %3;" : "=l"(d) : "l"(a), "l"(b), "l"(c));
    return d;
}
__device__ __forceinline__ unsigned long long add2u(unsigned long long a, unsigned long long b) {
    unsigned long long d;
    asm("add.rn.f32x2 %0, %1, %2;" : "=l"(d) : "l"(a), "l"(b));
    return d;
}
__device__ __forceinline__ float2 upk(unsigned long long u) {
    float lo, hi;
    asm("mov.b64 {%0, %1}, %2;" : "=f"(lo), "=f"(hi) : "l"(u));
    return make_float2(lo, hi);
}

// float4-interleaved transposed weights:  g_sw1T4[((i/4)*256 + h)*4 + (i%4)] = sw1[h][i]
__device__ float g_sw1T4[48 * 256 * 4];
__device__ float g_mw1T4[48 * 256 * 4];
__device__ float g_sw1last[256];          // sw1[h][192]
__device__ float g_sw2T4[64 * 64 * 4];    // [((h/4)*64 + d)*4 + h%4] = sw2[d][h]
__device__ float g_mw2T4[64 * 64 * 4];

// Partial means scratch: 512 half-bn blocks
__device__ float g_ph [512 * 64];
__device__ float g_pp [512 * 64];
__device__ float g_phb[512 * 32];
__device__ float g_pd [512];
__device__ float g_pmg[512];

// mod MLP layer-2 partials: [bn][q][100] (bias folded into q=0; raw, pre-sigmoid)
__device__ float g_l2p[256 * 4 * 100];

// per-nc neuron_id dot products: [nc][hh][c]  (c-minor; shared across the 4 batches)
__device__ float g_ndot_s[64 * 256 * 8];
__device__ float g_ndot_m[64 * 256 * 8];

#define MEANS_BLOCKS 512
#define PREP_BLOCKS  129

// ---------------- K1: partial means (blocks 0..511) + weight repack (512..640) ----------------
__global__ __launch_bounds__(256)
void means_prep_kernel(const float* __restrict__ h,
                       const float* __restrict__ primitives_state,
                       const float* __restrict__ hebbian_traces,
                       const float* __restrict__ decay_logit,
                       const float* __restrict__ msg_magnitude,
                       const float* __restrict__ sw1,
                       const float* __restrict__ mw1,
                       const float* __restrict__ sw2,
                       const float* __restrict__ mw2)
{
    const int tid = threadIdx.x;

    if (blockIdx.x >= MEANS_BLOCKS) {
        int pt = (blockIdx.x - MEANS_BLOCKS) * 256 + tid;
        if (pt < 12288) {
            int i4 = pt >> 8, hh = pt & 255;
            float4 v = make_float4(sw1[hh * 193 + i4 * 4 + 0], sw1[hh * 193 + i4 * 4 + 1],
                                   sw1[hh * 193 + i4 * 4 + 2], sw1[hh * 193 + i4 * 4 + 3]);
            *(float4*)&g_sw1T4[pt * 4] = v;
        } else if (pt < 24576) {
            int q = pt - 12288, i4 = q >> 8, hh = q & 255;
            float4 v = make_float4(mw1[hh * 192 + i4 * 4 + 0], mw1[hh * 192 + i4 * 4 + 1],
                                   mw1[hh * 192 + i4 * 4 + 2], mw1[hh * 192 + i4 * 4 + 3]);
            *(float4*)&g_mw1T4[q * 4] = v;
        } else if (pt < 28672) {
            int q = pt - 24576, h4 = q >> 6, d = q & 63;
            float4 v = make_float4(sw2[d * 256 + h4 * 4 + 0], sw2[d * 256 + h4 * 4 + 1],
                                   sw2[d * 256 + h4 * 4 + 2], sw2[d * 256 + h4 * 4 + 3]);
            *(float4*)&g_sw2T4[q * 4] = v;
        } else if (pt < 32768) {
            int q = pt - 28672, h4 = q >> 6, d = q & 63;
            float4 v = make_float4(mw2[d * 256 + h4 * 4 + 0], mw2[d * 256 + h4 * 4 + 1],
                                   mw2[d * 256 + h4 * 4 + 2], mw2[d * 256 + h4 * 4 + 3]);
            *(float4*)&g_mw2T4[q * 4] = v;
        } else if (pt < 33024) {
            int hh = pt - 32768;
            g_sw1last[hh] = sw1[hh * 193 + 192];
        }
        return;
    }

    __shared__ float s_h[1024];
    __shared__ float s_p[1024];
    __shared__ float s_b[1024];

    const int bn   = blockIdx.x >> 1;
    const int half = blockIdx.x & 1;
    const int c0   = half * 128;
    const int lane = tid & 31;
    const int warp = tid >> 5;
    const int pidx = blockIdx.x;

    const float4* hp4 = (const float4*)(h                + (long)bn * CDIM * DDIM + (long)c0 * DDIM);
    const float4* pp4 = (const float4*)(primitives_state + (long)bn * CDIM * DDIM + (long)c0 * DDIM);
    const float4* hb4 = (const float4*)(hebbian_traces   + (long)bn * CDIM * KDIM + (long)c0 * KDIM);

    const int v16 = tid & 15;
    const int cgr = tid >> 4;
    const int v8  = tid & 7;
    const int cb  = tid >> 3;

    float4 ha[8], pa[8], ba[4];
    #pragma unroll
    for (int j = 0; j < 8; j++) ha[j] = hp4[(cgr + 16 * j) * 16 + v16];
    #pragma unroll
    for (int j = 0; j < 8; j++) pa[j] = pp4[(cgr + 16 * j) * 16 + v16];
    #pragma unroll
    for (int j = 0; j < 4; j++) ba[j] = hb4[(cb + 32 * j) * 8 + v8];

    if (warp == 0) {
        const float* dl = decay_logit + (long)bn * CDIM + c0;
        float v = dl[lane] + dl[lane + 32] + dl[lane + 64] + dl[lane + 96];
        #pragma unroll
        for (int off = 16; off; off >>= 1) v += __shfl_down_sync(0xffffffffu, v, off);
        if (lane == 0) g_pd[pidx] = v;
    } else if (warp == 1) {
        const float* mg = msg_magnitude + (long)bn * CDIM + c0;
        float v = mg[lane] + mg[lane + 32] + mg[lane + 64] + mg[lane + 96];
        #pragma unroll
        for (int off = 16; off; off >>= 1) v += __shfl_down_sync(0xffffffffu, v, off);
        if (lane == 0) g_pmg[pidx] = v;
    }

    float4 hs, ps, bs;
    hs.x = ((ha[0].x + ha[1].x) + (ha[2].x + ha[3].x)) + ((ha[4].x + ha[5].x) + (ha[6].x + ha[7].x));
    hs.y = ((ha[0].y + ha[1].y) + (ha[2].y + ha[3].y)) + ((ha[4].y + ha[5].y) + (ha[6].y + ha[7].y));
    hs.z = ((ha[0].z + ha[1].z) + (ha[2].z + ha[3].z)) + ((ha[4].z + ha[5].z) + (ha[6].z + ha[7].z));
    hs.w = ((ha[0].w + ha[1].w) + (ha[2].w + ha[3].w)) + ((ha[4].w + ha[5].w) + (ha[6].w + ha[7].w));
    ps.x = ((pa[0].x + pa[1].x) + (pa[2].x + pa[3].x)) + ((pa[4].x + pa[5].x) + (pa[6].x + pa[7].x));
    ps.y = ((pa[0].y + pa[1].y) + (pa[2].y + pa[3].y)) + ((pa[4].y + pa[5].y) + (pa[6].y + pa[7].y));
    ps.z = ((pa[0].z + pa[1].z) + (pa[2].z + pa[3].z)) + ((pa[4].z + pa[5].z) + (pa[6].z + pa[7].z));
    ps.w = ((pa[0].w + pa[1].w) + (pa[2].w + pa[3].w)) + ((pa[4].w + pa[5].w) + (pa[6].w + pa[7].w));
    bs.x = (ba[0].x + ba[1].x) + (ba[2].x + ba[3].x);
    bs.y = (ba[0].y + ba[1].y) + (ba[2].y + ba[3].y);
    bs.z = (ba[0].z + ba[1].z) + (ba[2].z + ba[3].z);
    bs.w = (ba[0].w + ba[1].w) + (ba[2].w + ba[3].w);

    *(float4*)&s_h[cgr * 64 + v16 * 4] = hs;
    *(float4*)&s_p[cgr * 64 + v16 * 4] = ps;
    *(float4*)&s_b[cb * 32 + v8 * 4]   = bs;
    __syncthreads();

    if (tid < 64) {
        float t = 0.f;
        #pragma unroll
        for (int g = 0; g < 16; g++) t += s_h[g * 64 + tid];
        g_ph[pidx * 64 + tid] = t;
    } else if (tid < 128) {
        int d = tid - 64;
        float t = 0.f;
        #pragma unroll
        for (int g = 0; g < 16; g++) t += s_p[g * 64 + d];
        g_pp[pidx * 64 + d] = t;
    } else if (tid < 160) {
        int k = tid - 128;
        float t = 0.f;
        #pragma unroll
        for (int c2 = 0; c2 < 32; c2++) t += s_b[c2 * 32 + k];
        g_phb[pidx * 32 + k] = t;
    }
}

// ---------------- K2: mod MLP; grid 512 = (nc x 4 quarters x 2 batch-pairs); PDL on K1 ----------------
__global__ __launch_bounds__(256)
void modmlp_kernel(const float* __restrict__ mod_w1,
                   const float* __restrict__ mod_b1,
                   const float* __restrict__ mod_w2,
                   const float* __restrict__ mod_b2,
                   const float* __restrict__ neuron_id)
{
    __shared__ float s_min[2][232];
    __shared__ float s_hid[2][64];
    __shared__ float s_mm[2];
    __shared__ __align__(16) float s_nid[8][64];
    __shared__ float s_ps[4][512];
    __shared__ float s_pm[4][512];

    const int tid  = threadIdx.x;
    const int warp = tid >> 5;
    const int lane = tid & 31;
    const int nc   = blockIdx.x & 63;
    const int q    = (blockIdx.x >> 6) & 3;
    const int bp   = blockIdx.x >> 8;
    const float inv = 1.0f / CDIM;

    if (bp == 0) {
        int c = tid >> 5, d0 = (tid & 31) * 2;
        *(float2*)&s_nid[c][d0] = *(const float2*)&neuron_id[((long)nc * CDIM + (CDIM - ALPHA) + c) * DDIM + d0];
    }

    cudaGridDependencySynchronize();

    {
        int b2 = tid >> 7, r = tid & 127;
        int b  = bp * 2 + b2;
        int p0 = ((b * NCB + nc) << 1);
        if (r < 64) {
            s_min[b2][32 + r] = (g_ph[p0 * 64 + r] + g_ph[(p0 + 1) * 64 + r]) * inv;
        } else {
            int d = r - 64;
            s_min[b2][97 + d] = (g_pp[p0 * 64 + d] + g_pp[(p0 + 1) * 64 + d]) * inv;
        }
        if (tid < 64) {
            int bb = tid >> 5, k = tid & 31;
            int p = (((bp * 2 + bb) * NCB + nc) << 1);
            s_min[bb][k] = (g_phb[p * 32 + k] + g_phb[(p + 1) * 32 + k]) * inv;
        } else if (tid < 66) {
            int bb = tid - 64;
            int p = (((bp * 2 + bb) * NCB + nc) << 1);
            s_min[bb][96] = (g_pd[p] + g_pd[p + 1]) * inv;
        } else if (tid < 68) {
            int bb = tid - 66;
            int p = (((bp * 2 + bb) * NCB + nc) << 1);
            s_mm[bb] = (g_pmg[p] + g_pmg[p + 1]) * inv;
        }
    }
    __syncthreads();
    {
        int b2 = tid >> 7, r = tid & 127;
        if (r < 64) s_min[b2][161 + r] = s_mm[b2];
    }
    __syncthreads();

    if (bp == 0) {
        int hhl = tid & 63, ig = tid >> 6;
        int hh = q * 64 + hhl;
        float accs[8], accm[8];
        #pragma unroll
        for (int c = 0; c < 8; c++) { accs[c] = 0.f; accm[c] = 0.f; }
        #pragma unroll
        for (int s = 0; s < 4; s++) {
            int i4 = 32 + ig * 4 + s;
            int i  = (i4 - 32) * 4;
            float4 ws = *(const float4*)&g_sw1T4[(i4 * 256 + hh) * 4];
            float4 wm = *(const float4*)&g_mw1T4[(i4 * 256 + hh) * 4];
            #pragma unroll
            for (int c = 0; c < 8; c++) {
                float4 nv = *(const float4*)&s_nid[c][i];
                accs[c] += nv.x * ws.x + nv.y * ws.y + nv.z * ws.z + nv.w * ws.w;
                accm[c] += nv.x * wm.x + nv.y * wm.y + nv.z * wm.z + nv.w * wm.w;
            }
        }
        #pragma unroll
        for (int c = 0; c < 8; c++) {
            s_ps[ig][hhl * 8 + c] = accs[c];
            s_pm[ig][hhl * 8 + c] = accm[c];
        }
        __syncthreads();
        for (int o = tid; o < 512; o += 256) {
            int hhl2 = o >> 3;
            int hh2 = q * 64 + hhl2;
            int c = o & 7;
            g_ndot_s[((long)nc * 256 + hh2) * 8 + c] = s_ps[0][o] + s_ps[1][o] + s_ps[2][o] + s_ps[3][o];
            g_ndot_m[((long)nc * 256 + hh2) * 8 + c] = s_pm[0][o] + s_pm[1][o] + s_pm[2][o] + s_pm[3][o];
        }
    }

    for (int r = 0; r < 8; r++) {
        int rloc = warp * 8 + r;
        int h0 = q * 64 + rloc;
        const float* row = mod_w1 + ((long)nc * HDIM + h0) * MODI;
        float a0 = 0.f, a1 = 0.f;
        #pragma unroll
        for (int j = 0; j < 7; j++) {
            int i = lane + 32 * j;
            float w = row[i];
            a0 += w * s_min[0][i];
            a1 += w * s_min[1][i];
        }
        if (lane == 0) {
            float w = row[224];
            a0 += w * s_min[0][224];
            a1 += w * s_min[1][224];
        }
        #pragma unroll
        for (int off = 16; off; off >>= 1) {
            a0 += __shfl_down_sync(0xffffffffu, a0, off);
            a1 += __shfl_down_sync(0xffffffffu, a1, off);
        }
        if (lane == 0) {
            float bias = mod_b1[nc * HDIM + h0];
            s_hid[0][rloc] = ftanh(a0 + bias);
            s_hid[1][rloc] = ftanh(a1 + bias);
        }
    }
    __syncthreads();

    if (tid < 194) {
        int o = tid >> 1, bl = tid & 1;
        int b = bp * 2 + bl;
        const float* w2c = mod_w2 + (long)nc * HDIM * MODO + (long)(q * 64) * MODO + o;
        float a = 0.f;
        #pragma unroll 8
        for (int hh = 0; hh < 64; hh++) a += w2c[hh * MODO] * s_hid[bl][hh];
        if (q == 0) a += mod_b2[nc * MODO + o];
        g_l2p[(((long)b * NCB + nc) * 4 + q) * 100 + o] = a;
    }
}

// ---------------- K3: per-cell pipeline; 256 threads, full-i per thread, PDL on K2 ----------------
__global__ __launch_bounds__(256, 2)
void cellmem_kernel(
    const float* __restrict__ h,
    const float* __restrict__ prev_messages,
    const float* __restrict__ state_b1,
    const float* __restrict__ state_b2,
    const float* __restrict__ msg_b1,
    const float* __restrict__ msg_b2,
    const int*   __restrict__ conn_indices,
    float* __restrict__ out)
{
    __shared__ float s_wsig[32];
    __shared__ __align__(16) float s_prim[64];
    __shared__ float s_scal[2];
    __shared__ int   s_conn[256];
    __shared__ __align__(16) float s_hvT[512];     // [d][c]
    __shared__ __align__(16) float s_invT[512];    // [d][c]
    __shared__ __align__(16) float s_hnewT[512];   // [d][c]
    __shared__ __align__(16) float s_scratch[2048];// [hq][d][c]  4*64*8
    __shared__ __align__(16) float s_t[2048];      // [hh][c]
    __shared__ __align__(16) float s_acc8T[512];   // [d][c]

    const int tid  = threadIdx.x;
    const int warp = tid >> 5;
    const int lane = tid & 31;
    const int b    = blockIdx.x >> 6;
    const int nc   = blockIdx.x & 63;
    const long bn  = (long)b * NCB + nc;

    const float* hp = h             + bn * CDIM * DDIM;
    const float* pm = prev_messages + bn * CDIM * DDIM;

    // ---- PDL prologue: inputs only (conn, h) ----
    {
        int cc = tid >> 5, k = tid & 31;
        s_conn[tid] = conn_indices[((long)nc * CDIM + (CDIM - ALPHA) + cc) * KDIM + k];
    }
    #pragma unroll
    for (int r = 0; r < 2; r++) {
        int idx = tid + 256 * r;
        int c = idx >> 6, d = idx & 63;
        s_hvT[d * 8 + c] = hp[((CDIM - ALPHA) + c) * DDIM + d];
    }

    cudaGridDependencySynchronize();

    // ---------- P1 ----------
    if (tid < MODO) {
        float v = g_l2p[(bn * 4 + 0) * 100 + tid] + g_l2p[(bn * 4 + 1) * 100 + tid]
                + g_l2p[(bn * 4 + 2) * 100 + tid] + g_l2p[(bn * 4 + 3) * 100 + tid];
        if (tid < KDIM)        s_wsig[tid] = sigm(v);
        else if (tid == KDIM) { s_scal[0] = v; s_scal[1] = sigm(v); }
        else                   s_prim[tid - KDIM - 1] = v;
    }
    __syncthreads();

    // ---------- P5: gather (warp per cell, all 32 k) ----------
    {
        int cc = warp;
        float ax = 0.f, ay = 0.f, bx = 0.f, by = 0.f;
        #pragma unroll 4
        for (int k = 0; k < KDIM; k += 2) {
            const float2* p0 = (const float2*)(pm + (long)s_conn[cc * KDIM + k] * DDIM);
            const float2* p1 = (const float2*)(pm + (long)s_conn[cc * KDIM + k + 1] * DDIM);
            float w0 = s_wsig[k], w1 = s_wsig[k + 1];
            float2 v0 = p0[lane], v1 = p1[lane];
            ax += w0 * v0.x; ay += w0 * v0.y;
            bx += w1 * v1.x; by += w1 * v1.y;
        }
        s_invT[(lane * 2) * 8 + cc]     = ax + bx;
        s_invT[(lane * 2 + 1) * 8 + cc] = ay + by;
    }
    __syncthreads();

    // ---------- P6: state hidden (thread = hh, full i range) ----------
    {
        int hh = tid;
        unsigned long long acc2[4];
        {
            const ulonglong2* np = (const ulonglong2*)&g_ndot_s[((long)nc * 256 + hh) * 8];
            ulonglong2 n01 = np[0], n23 = np[1];
            acc2[0] = n01.x; acc2[1] = n01.y; acc2[2] = n23.x; acc2[3] = n23.y;
        }
        float pdot = 0.f;
        #pragma unroll
        for (int i4 = 0; i4 < 16; i4++) {
            int i = i4 * 4;
            float wa[4], wb[4];
            *(float4*)wa = *(const float4*)&g_sw1T4[(i4 * 256 + hh) * 4];
            *(float4*)wb = *(const float4*)&g_sw1T4[((i4 + 16) * 256 + hh) * 4];
            float4 pv = *(const float4*)&s_prim[i];
            pdot += pv.x * wa[0] * 0.f;  // placeholder removed below
            pdot += pv.x * wb[0] + pv.y * wb[1] + pv.z * wb[2] + pv.w * wb[3];
            #pragma unroll
            for (int e = 0; e < 4; e++) {
                unsigned long long w2 = pk(wa[e], wa[e]);
                const ulonglong2* ivp = (const ulonglong2*)&s_invT[(i + e) * 8];
                ulonglong2 p01 = ivp[0], p23 = ivp[1];
                acc2[0] = ffma2u(w2, p01.x, acc2[0]);
                acc2[1] = ffma2u(w2, p01.y, acc2[1]);
                acc2[2] = ffma2u(w2, p23.x, acc2[2]);
                acc2[3] = ffma2u(w2, p23.y, acc2[3]);
            }
        }
        float extra = pdot + state_b1[hh] + s_scal[0] * g_sw1last[hh];
        #pragma unroll
        for (int j = 0; j < 4; j++) {
            float2 r = upk(acc2[j]);
            s_t[hh * 8 + 2 * j]     = ftanh(r.x + extra);
            s_t[hh * 8 + 2 * j + 1] = ftanh(r.y + extra);
        }
    }
    __syncthreads();

    // ---------- P7: update + h_new (thread = (d, hq), 4-way hq split) ----------
    {
        int d = tid & 63, hq = tid >> 6;
        unsigned long long z = pk(0.f, 0.f);
        unsigned long long acc2[4] = {z, z, z, z};
        #pragma unroll
        for (int s = 0; s < 16; s++) {
            int h4 = hq * 16 + s, hh = h4 * 4;
            float wa[4];
            *(float4*)wa = *(const float4*)&g_sw2T4[(h4 * 64 + d) * 4];
            #pragma unroll
            for (int e = 0; e < 4; e++) {
                unsigned long long w2 = pk(wa[e], wa[e]);
                const ulonglong2* tp = (const ulonglong2*)&s_t[(hh + e) * 8];
                ulonglong2 p01 = tp[0], p23 = tp[1];
                acc2[0] = ffma2u(w2, p01.x, acc2[0]);
                acc2[1] = ffma2u(w2, p01.y, acc2[1]);
                acc2[2] = ffma2u(w2, p23.x, acc2[2]);
                acc2[3] = ffma2u(w2, p23.y, acc2[3]);
            }
        }
        ulonglong2* op = (ulonglong2*)&s_scratch[hq * 512 + d * 8];
        op[0] = make_ulonglong2(acc2[0], acc2[1]);
        op[1] = make_ulonglong2(acc2[2], acc2[3]);
    }
    __syncthreads();
    {
        float ds = s_scal[1];
        #pragma unroll
        for (int r = 0; r < 2; r++) {
            int idx = tid + 256 * r;
            int d = idx >> 3;
            float a = s_scratch[idx] + s_scratch[512 + idx] + s_scratch[1024 + idx] + s_scratch[1536 + idx]
                    + state_b2[d];
            s_hnewT[idx] = ds * s_hvT[idx] + (1.f - ds) * ftanh(a);
        }
    }
    __syncthreads();

    // ---------- P8: msg hidden (thread = hh, full i range) ----------
    {
        int hh = tid;
        unsigned long long acc2[4];
        {
            const ulonglong2* np = (const ulonglong2*)&g_ndot_m[((long)nc * 256 + hh) * 8];
            ulonglong2 n01 = np[0], n23 = np[1];
            acc2[0] = n01.x; acc2[1] = n01.y; acc2[2] = n23.x; acc2[3] = n23.y;
        }
        float pdot = 0.f;
        #pragma unroll
        for (int i4 = 0; i4 < 16; i4++) {
            int i = i4 * 4;
            float wa[4], wb[4];
            *(float4*)wa = *(const float4*)&g_mw1T4[(i4 * 256 + hh) * 4];
            *(float4*)wb = *(const float4*)&g_mw1T4[((i4 + 16) * 256 + hh) * 4];
            float4 pv = *(const float4*)&s_prim[i];
            pdot += pv.x * wb[0] + pv.y * wb[1] + pv.z * wb[2] + pv.w * wb[3];
            #pragma unroll
            for (int e = 0; e < 4; e++) {
                unsigned long long w2 = pk(wa[e], wa[e]);
                const ulonglong2* ivp = (const ulonglong2*)&s_hnewT[(i + e) * 8];
                ulonglong2 p01 = ivp[0], p23 = ivp[1];
                acc2[0] = ffma2u(w2, p01.x, acc2[0]);
                acc2[1] = ffma2u(w2, p01.y, acc2[1]);
                acc2[2] = ffma2u(w2, p23.x, acc2[2]);
                acc2[3] = ffma2u(w2, p23.y, acc2[3]);
            }
        }
        float extra = pdot + msg_b1[hh];
        #pragma unroll
        for (int j = 0; j < 4; j++) {
            float2 r = upk(acc2[j]);
            s_t[hh * 8 + 2 * j]     = ftanh(r.x + extra);
            s_t[hh * 8 + 2 * j + 1] = ftanh(r.y + extra);
        }
    }
    __syncthreads();

    // ---------- P9: msg out + readout ----------
    {
        int d = tid & 63, hq = tid >> 6;
        unsigned long long z = pk(0.f, 0.f);
        unsigned long long acc2[4] = {z, z, z, z};
        #pragma unroll
        for (int s = 0; s < 16; s++) {
            int h4 = hq * 16 + s, hh = h4 * 4;
            float wa[4];
            *(float4*)wa = *(const float4*)&g_mw2T4[(h4 * 64 + d) * 4];
            #pragma unroll
            for (int e = 0; e < 4; e++) {
                unsigned long long w2 = pk(wa[e], wa[e]);
                const ulonglong2* tp = (const ulonglong2*)&s_t[(hh + e) * 8];
                ulonglong2 p01 = tp[0], p23 = tp[1];
                acc2[0] = ffma2u(w2, p01.x, acc2[0]);
                acc2[1] = ffma2u(w2, p01.y, acc2[1]);
                acc2[2] = ffma2u(w2, p23.x, acc2[2]);
                acc2[3] = ffma2u(w2, p23.y, acc2[3]);
            }
        }
        ulonglong2* op = (ulonglong2*)&s_scratch[hq * 512 + d * 8];
        op[0] = make_ulonglong2(acc2[0], acc2[1]);
        op[1] = make_ulonglong2(acc2[2], acc2[3]);
    }
    __syncthreads();
    {
        #pragma unroll
        for (int r = 0; r < 2; r++) {
            int idx = tid + 256 * r;
            int d = idx >> 3;
            float a = s_scratch[idx] + s_scratch[512 + idx] + s_scratch[1024 + idx] + s_scratch[1536 + idx]
                    + msg_b2[d];
            s_acc8T[idx] = ftanh(a);
        }
    }
    __syncthreads();
    if (tid < 64) {
        float4 a0 = *(const float4*)&s_acc8T[tid * 8];
        float4 a1 = *(const float4*)&s_acc8T[tid * 8 + 4];
        out[(long)b * (NCB * DDIM) + nc * DDIM + tid] =
            ((a0.x + a0.y) + (a0.z + a0.w) + (a1.x + a1.y) + (a1.z + a1.w)) * 0.125f;
    }
}

extern "C" void kernel_launch(void* const* d_in, const int* in_sizes, int n_in,
                              void* d_out, int out_size)
{
    const float* h          = (const float*)d_in[0];
    const float* prev_msg   = (const float*)d_in[1];
    const float* decay      = (const float*)d_in[2];
    const float* prim       = (const float*)d_in[3];
    const float* hebb       = (const float*)d_in[4];
    const float* msgmag     = (const float*)d_in[5];
    // d_in[6] = cc_signals : dead (injection hits cells < ALPHA; output reads cells >= C-ALPHA)
    const float* state_w1   = (const float*)d_in[7];
    const float* state_b1   = (const float*)d_in[8];
    const float* state_w2   = (const float*)d_in[9];
    const float* state_b2   = (const float*)d_in[10];
    const float* msg_w1     = (const float*)d_in[11];
    const float* msg_b1     = (const float*)d_in[12];
    const float* msg_w2     = (const float*)d_in[13];
    const float* msg_b2     = (const float*)d_in[14];
    const float* mod_w1     = (const float*)d_in[15];
    const float* mod_b1     = (const float*)d_in[16];
    const float* mod_w2     = (const float*)d_in[17];
    const float* mod_b2     = (const float*)d_in[18];
    const float* neuron_id  = (const float*)d_in[19];
    const int*   conn       = (const int*)d_in[20];
    float* outp             = (float*)d_out;

    means_prep_kernel<<<MEANS_BLOCKS + PREP_BLOCKS, 256>>>(
        h, prim, hebb, decay, msgmag, state_w1, msg_w1, state_w2, msg_w2);

    {
        cudaLaunchConfig_t cfg = {};
        cfg.gridDim  = dim3(512, 1, 1);
        cfg.blockDim = dim3(256, 1, 1);
        cudaLaunchAttribute attrs[1];
        attrs[0].id = cudaLaunchAttributeProgrammaticStreamSerialization;
        attrs[0].val.programmaticStreamSerializationAllowed = 1;
        cfg.attrs = attrs;
        cfg.numAttrs = 1;
        cudaLaunchKernelEx(&cfg, modmlp_kernel, mod_w1, mod_b1, mod_w2, mod_b2, neuron_id);
    }

    {
        cudaLaunchConfig_t cfg = {};
        cfg.gridDim  = dim3(256, 1, 1);
        cfg.blockDim = dim3(256, 1, 1);
        cudaLaunchAttribute attrs[1];
        attrs[0].id = cudaLaunchAttributeProgrammaticStreamSerialization;
        attrs[0].val.programmaticStreamSerializationAllowed = 1;
        cfg.attrs = attrs;
        cfg.numAttrs = 1;
        cudaLaunchKernelEx(&cfg, cellmem_kernel, h, prev_msg,
                           state_b1, state_b2, msg_b1, msg_b2, conn, outp);
    }
}